// round 13
// baseline (speedup 1.0000x reference)
#include <cuda_runtime.h>
#include <cstdint>
#include <math.h>

#define SCALEF 0.125f     // DH^-0.5
#define EPSF   1e-8f
#define LNEPS  1e-5f

// -------- scratch (device globals: allocation-free) --------
__device__ float g_stats[2 * 131072];     // per-row mean,rstd of inputs
__device__ float g_lnx[33554432];         // LN(inputs) [b][j][256]
__device__ float g_L[8192];               // L[b][c] = sum_j lnx
__device__ float g_P[4 * 256 * 256];      // P_h = Wq_h^T Wk_h
__device__ float g_t[1024 * 256];         // t[(b,ih)][c] (SCALE folded)
__device__ float g_upart[64 * 1024 * 256];// u partials [js][(b,ih)][c]
__device__ float g_rowsum[1024];          // [b][ih]
__device__ float g_fill[65536];           // fillers
__device__ float g_f[65536];              // LN(fillers)
__device__ float g_upd[65536];            // updates
__device__ float g_gates[2 * 256 * 768];  // [gi|gh]

// ---------------- packed f32x2 helpers ----------------
__device__ __forceinline__ unsigned long long ffma2(unsigned long long a,
                                                    unsigned long long b,
                                                    unsigned long long c) {
    unsigned long long d;
    asm("fma.rn.f32x2 %0, %1, %2, %3;" : "=l"(d) : "l"(a), "l"(b), "l"(c));
    return d;
}
__device__ __forceinline__ unsigned long long bcast2(float x) {
    unsigned u = __float_as_uint(x);
    return ((unsigned long long)u << 32) | (unsigned long long)u;
}
__device__ __forceinline__ float lo2(unsigned long long v) { return __uint_as_float((unsigned)v); }
__device__ __forceinline__ float hi2(unsigned long long v) { return __uint_as_float((unsigned)(v >> 32)); }

// ---------------- row stats (also zero g_L) ----------------
__global__ void k_rowstats(const float* __restrict__ x) {
    int gid = blockIdx.x * blockDim.x + threadIdx.x;
    if (gid < 8192) g_L[gid] = 0.f;
    int warp = gid >> 5;
    int lane = threadIdx.x & 31;
    const float* r = x + (size_t)warp * 256;
    float v[8];
    float s = 0.f;
#pragma unroll
    for (int u = 0; u < 8; u++) { v[u] = r[lane + 32 * u]; s += v[u]; }
#pragma unroll
    for (int o = 16; o > 0; o >>= 1) s += __shfl_xor_sync(0xffffffffu, s, o);
    float m = s * (1.f / 256.f);
    float ss = 0.f;
#pragma unroll
    for (int u = 0; u < 8; u++) { float d = v[u] - m; ss += d * d; }
#pragma unroll
    for (int o = 16; o > 0; o >>= 1) ss += __shfl_xor_sync(0xffffffffu, ss, o);
    if (lane == 0) {
        g_stats[2 * warp + 0] = m;
        g_stats[2 * warp + 1] = rsqrtf(ss * (1.f / 256.f) + LNEPS);
    }
}

// ---------------- LN(inputs) + column sums L ----------------
__global__ void __launch_bounds__(256)
k_lnx(const float* __restrict__ x, const float* __restrict__ g,
      const float* __restrict__ b) {
    int bb = blockIdx.x, jc = blockIdx.y;     // grid (32, 32)
    int t = threadIdx.x;
    float gg = g[t], bv = b[t];
    int row0 = bb * 4096 + jc * 128;
    float csum = 0.f;
#pragma unroll 4
    for (int r = 0; r < 128; r++) {
        int row = row0 + r;
        float m = g_stats[2 * row], rs = g_stats[2 * row + 1];
        float v = x[(size_t)row * 256 + t];
        float o = (v - m) * rs * gg + bv;
        g_lnx[(size_t)row * 256 + t] = o;
        csum += o;
    }
    atomicAdd(&g_L[bb * 256 + t], csum);
}

// ---------------- P_h = Wq_h^T @ Wk_h (once) ----------------
__global__ void __launch_bounds__(256)
k_pcomp(const float* __restrict__ Wq, const float* __restrict__ Wk) {
    int h = blockIdx.x, et = blockIdx.y, ct = blockIdx.z;
    int e0 = et * 64, c0 = ct * 64;
    int t = threadIdx.x;
    int tx = t & 15, ty = t >> 4;

    __shared__ float Qs[64][65];
    __shared__ float Ks[64][65];
    int d = t >> 2, sg = (t & 3) * 16;
#pragma unroll
    for (int q = 0; q < 4; q++) {
        float4 vq = *(const float4*)(Wq + (size_t)(h * 64 + d) * 256 + e0 + sg + q * 4);
        Qs[d][sg + q * 4 + 0] = vq.x; Qs[d][sg + q * 4 + 1] = vq.y;
        Qs[d][sg + q * 4 + 2] = vq.z; Qs[d][sg + q * 4 + 3] = vq.w;
        float4 vk = *(const float4*)(Wk + (size_t)(h * 64 + d) * 256 + c0 + sg + q * 4);
        Ks[d][sg + q * 4 + 0] = vk.x; Ks[d][sg + q * 4 + 1] = vk.y;
        Ks[d][sg + q * 4 + 2] = vk.z; Ks[d][sg + q * 4 + 3] = vk.w;
    }
    __syncthreads();
    float acc[4][4];
#pragma unroll
    for (int i = 0; i < 4; i++)
#pragma unroll
        for (int j = 0; j < 4; j++) acc[i][j] = 0.f;
    for (int dd = 0; dd < 64; dd++) {
        float a[4], bb[4];
#pragma unroll
        for (int i = 0; i < 4; i++) a[i] = Qs[dd][ty + 16 * i];
#pragma unroll
        for (int j = 0; j < 4; j++) bb[j] = Ks[dd][tx + 16 * j];
#pragma unroll
        for (int i = 0; i < 4; i++)
#pragma unroll
            for (int j = 0; j < 4; j++) acc[i][j] += a[i] * bb[j];
    }
#pragma unroll
    for (int i = 0; i < 4; i++)
#pragma unroll
        for (int j = 0; j < 4; j++)
            g_P[(size_t)h * 65536 + (size_t)(e0 + ty + 16 * i) * 256 + c0 + tx + 16 * j] = acc[i][j];
}

// ---------------- LN(fillers) + zero rowsum (+copy cond on iter0) ----------
__global__ void k_lnfill(const float* __restrict__ g, const float* __restrict__ b,
                         const float* __restrict__ cond, int first) {
    int t = threadIdx.x;
    int gt = blockIdx.x * 256 + t;
    if (gt < 1024) g_rowsum[gt] = 0.f;

    int row  = blockIdx.x * 8 + (t >> 5);   // 256 rows
    int lane = t & 31;
    const float* r = (first ? cond : g_fill) + (size_t)row * 256;
    float v[8];
    float s = 0.f;
#pragma unroll
    for (int u = 0; u < 8; u++) { v[u] = r[lane + 32 * u]; s += v[u]; }
#pragma unroll
    for (int o = 16; o > 0; o >>= 1) s += __shfl_xor_sync(0xffffffffu, s, o);
    float m = s * (1.f / 256.f);
    float ss = 0.f;
#pragma unroll
    for (int u = 0; u < 8; u++) { float d = v[u] - m; ss += d * d; }
#pragma unroll
    for (int o = 16; o > 0; o >>= 1) ss += __shfl_xor_sync(0xffffffffu, ss, o);
    float rstd = rsqrtf(ss * (1.f / 256.f) + LNEPS);
#pragma unroll
    for (int u = 0; u < 8; u++) {
        int c = lane + 32 * u;
        if (first) g_fill[row * 256 + c] = v[u];
        g_f[row * 256 + c] = (v[u] - m) * rstd * g[c] + b[c];
    }
}

// ---------------- t = SCALE * f @ P_h ----------------
__global__ void __launch_bounds__(256)
k_tgemm() {
    int b = blockIdx.x, ct = blockIdx.y;
    int c0 = ct * 64;
    int t = threadIdx.x;
    int ihx = t >> 3, c8 = (t & 7) * 8;
    int h = ihx & 3, i = ihx >> 2;

    __shared__ float fs[2048];
    __shared__ __align__(16) float Ps[4][32][68];

#pragma unroll
    for (int q = 0; q < 8; q++) fs[t + 256 * q] = g_f[b * 2048 + t + 256 * q];

    unsigned long long acc[4] = {0ull, 0ull, 0ull, 0ull};

    for (int ec = 0; ec < 8; ec++) {
        int e0 = ec * 32;
        __syncthreads();
#pragma unroll
        for (int q = 0; q < 8; q++) {
            int idx = t + 256 * q;
            int hh = idx >> 9, e = (idx >> 4) & 31, sg = idx & 15;
            float4 v = *(const float4*)(g_P + (size_t)hh * 65536 +
                                        (size_t)(e0 + e) * 256 + c0 + sg * 4);
            *(float4*)&Ps[hh][e][sg * 4] = v;
        }
        __syncthreads();
#pragma unroll
        for (int e = 0; e < 32; e++) {
            unsigned long long a = bcast2(fs[i * 256 + e0 + e]);
            ulonglong2 p0 = *(const ulonglong2*)&Ps[h][e][c8];
            ulonglong2 p1 = *(const ulonglong2*)&Ps[h][e][c8 + 4];
            acc[0] = ffma2(a, p0.x, acc[0]);
            acc[1] = ffma2(a, p0.y, acc[1]);
            acc[2] = ffma2(a, p1.x, acc[2]);
            acc[3] = ffma2(a, p1.y, acc[3]);
        }
    }
    int row = b * 32 + ihx;
#pragma unroll
    for (int q = 0; q < 4; q++) {
        g_t[(size_t)row * 256 + c0 + c8 + 2 * q]     = SCALEF * lo2(acc[q]);
        g_t[(size_t)row * 256 + c0 + c8 + 2 * q + 1] = SCALEF * hi2(acc[q]);
    }
}

// ---------------- fused: dots + inverted softmax + u-accumulation ------------
// grid (32 b, 64 js of 64 j), 256 threads, 105.5KB dyn smem -> 2 blocks/SM
// (16 warps/SM). Block's lnx slice T[64][260] loaded from global ONCE; both
// phases run from smem. Phase1 pack-free (natural f32x2 c-pairs).
__global__ void __launch_bounds__(256)
k_fused(int last, float* __restrict__ attn_out) {
    extern __shared__ __align__(16) float sm[];
    float* T   = sm;                          // [64][260] lnx tile
    float* dsm = sm + 64 * 260;               // [32][68] dots/attn
    float* ts  = sm + 64 * 260 + 32 * 68;     // [32][256] t rows (phase1)
    unsigned long long* ap = (unsigned long long*)ts;  // [32][64] packed attn (phase2)

    int b = blockIdx.x, js = blockIdx.y;
    int t = threadIdx.x;
    int ihq = t >> 5, lane = t & 31;          // ihq: 4-ih group (0..7)
    int j0 = js * 64;
    const float* lnxb = g_lnx + (size_t)b * 4096 * 256;

    // ---- load T (64x256) and ts (32x256) from global
#pragma unroll
    for (int q = 0; q < 16; q++) {
        int idx = t + 256 * q;                // float4 units 0..4095
        int j = idx >> 6, c4 = (idx & 63) * 4;
        *(float4*)&T[j * 260 + c4] = *(const float4*)(lnxb + (size_t)(j0 + j) * 256 + c4);
    }
#pragma unroll
    for (int q = 0; q < 8; q++) {
        int idx = t + 256 * q;                // 0..2047
        int ih = idx >> 6, c4 = (idx & 63) * 4;
        *(float4*)&ts[ih * 256 + c4] = *(const float4*)(g_t + (size_t)(b * 32 + ih) * 256 + c4);
    }
    __syncthreads();

    // ---- phase 1: dots[ih][j], ih = ihq*4..+4, j in {lane, lane+32}
    unsigned long long acc1[4][2];
#pragma unroll
    for (int ii = 0; ii < 4; ii++) { acc1[ii][0] = 0ull; acc1[ii][1] = 0ull; }

    const float* Trow0 = &T[lane * 260];
    const float* Trow1 = &T[(lane + 32) * 260];
    for (int c = 0; c < 256; c += 4) {        // 2 c-pairs per step
        ulonglong2 b0 = *(const ulonglong2*)(Trow0 + c);
        ulonglong2 b1 = *(const ulonglong2*)(Trow1 + c);
#pragma unroll
        for (int ii = 0; ii < 4; ii++) {
            ulonglong2 a = *(const ulonglong2*)&ts[(ihq * 4 + ii) * 256 + c];
            acc1[ii][0] = ffma2(a.x, b0.x, acc1[ii][0]);
            acc1[ii][0] = ffma2(a.y, b0.y, acc1[ii][0]);
            acc1[ii][1] = ffma2(a.x, b1.x, acc1[ii][1]);
            acc1[ii][1] = ffma2(a.y, b1.y, acc1[ii][1]);
        }
    }
#pragma unroll
    for (int ii = 0; ii < 4; ii++) {
        dsm[(ihq * 4 + ii) * 68 + lane]      = lo2(acc1[ii][0]) + hi2(acc1[ii][0]);
        dsm[(ihq * 4 + ii) * 68 + lane + 32] = lo2(acc1[ii][1]) + hi2(acc1[ii][1]);
    }
    __syncthreads();

    // ---- softmax over 32 (slot,head) per column j = t (t < 64)
    if (t < 64) {
        float vcol[32], mx = -1e30f;
#pragma unroll
        for (int ih = 0; ih < 32; ih++) { vcol[ih] = dsm[ih * 68 + t]; mx = fmaxf(mx, vcol[ih]); }
        float sum = 0.f;
#pragma unroll
        for (int ih = 0; ih < 32; ih++) { vcol[ih] = __expf(vcol[ih] - mx); sum += vcol[ih]; }
        float inv = 1.f / sum;
#pragma unroll
        for (int ih = 0; ih < 32; ih++) { vcol[ih] *= inv; dsm[ih * 68 + t] = vcol[ih]; }
        if (last) {
#pragma unroll
            for (int i = 0; i < 8; i++)
                attn_out[((size_t)b * 8 + i) * 4096 + j0 + t] =
                    0.25f * (vcol[4 * i] + vcol[4 * i + 1] + vcol[4 * i + 2] + vcol[4 * i + 3]);
        }
    }
    __syncthreads();

    // ---- pack attn into ap (overlays ts) + rowsum partials
    {
        int ih = t >> 3, jq = (t & 7) * 8;
        float rs = 0.f;
#pragma unroll
        for (int k = 0; k < 8; k++) {
            float a = dsm[ih * 68 + jq + k];
            rs += a;
            ap[ih * 64 + jq + k] = bcast2(a);
        }
        rs += __shfl_xor_sync(0xffffffffu, rs, 1);
        rs += __shfl_xor_sync(0xffffffffu, rs, 2);
        rs += __shfl_xor_sync(0xffffffffu, rs, 4);
        if ((t & 7) == 0) atomicAdd(&g_rowsum[b * 32 + ih], rs);
    }
    __syncthreads();

    // ---- phase 2: u[ih][c] += attn[ih][j] * T[j][c]; ih = ihq*4..+4, c = lane*8..+8
    unsigned long long acc2[4][4];
#pragma unroll
    for (int ii = 0; ii < 4; ii++)
#pragma unroll
        for (int q = 0; q < 4; q++) acc2[ii][q] = 0ull;

    for (int j = 0; j < 64; j += 2) {
        ulonglong2 bA0 = *(const ulonglong2*)&T[j * 260 + lane * 8];
        ulonglong2 bA1 = *(const ulonglong2*)&T[j * 260 + lane * 8 + 4];
        ulonglong2 bB0 = *(const ulonglong2*)&T[(j + 1) * 260 + lane * 8];
        ulonglong2 bB1 = *(const ulonglong2*)&T[(j + 1) * 260 + lane * 8 + 4];
#pragma unroll
        for (int ii = 0; ii < 4; ii++) {
            ulonglong2 a = *(const ulonglong2*)&ap[(ihq * 4 + ii) * 64 + j];
            acc2[ii][0] = ffma2(a.x, bA0.x, acc2[ii][0]);
            acc2[ii][1] = ffma2(a.x, bA0.y, acc2[ii][1]);
            acc2[ii][2] = ffma2(a.x, bA1.x, acc2[ii][2]);
            acc2[ii][3] = ffma2(a.x, bA1.y, acc2[ii][3]);
            acc2[ii][0] = ffma2(a.y, bB0.x, acc2[ii][0]);
            acc2[ii][1] = ffma2(a.y, bB0.y, acc2[ii][1]);
            acc2[ii][2] = ffma2(a.y, bB1.x, acc2[ii][2]);
            acc2[ii][3] = ffma2(a.y, bB1.y, acc2[ii][3]);
        }
    }

    // u partials (slice js; overwrite, no zeroing)
#pragma unroll
    for (int ii = 0; ii < 4; ii++) {
        float* dst = g_upart + ((size_t)(js * 1024) + b * 32 + ihq * 4 + ii) * 256 + lane * 8;
        *(float4*)dst       = make_float4(lo2(acc2[ii][0]), hi2(acc2[ii][0]),
                                          lo2(acc2[ii][1]), hi2(acc2[ii][1]));
        *(float4*)(dst + 4) = make_float4(lo2(acc2[ii][2]), hi2(acc2[ii][2]),
                                          lo2(acc2[ii][3]), hi2(acc2[ii][3]));
    }
}

// ---------------- upd = ((Σu + eps·L)/denom) @ Wv_h^T ----------------
__global__ void __launch_bounds__(256)
k_updproj(const float* __restrict__ Wv) {
    int b = blockIdx.x, dh2 = blockIdx.y;
    int t = threadIdx.x;
    int ihx = t >> 3, dq = (t & 7) * 4;
    int h = ihx & 3, i = ihx >> 2;
    int dbase = dh2 * 32;

    __shared__ __align__(16) float ss[32][256];
    __shared__ float Wvs[4][32][16];
    __shared__ float inv_s[32];

    if (t < 32) inv_s[t] = 1.f / (g_rowsum[b * 32 + t] + 4096.f * EPSF);
    __syncthreads();

#pragma unroll
    for (int q = 0; q < 8; q++) {
        int idx = t + 256 * q;
        int ih = idx >> 6, s4 = idx & 63;
        float4 Lv = *(const float4*)(g_L + b * 256 + s4 * 4);
        float4 a = make_float4(Lv.x * EPSF, Lv.y * EPSF, Lv.z * EPSF, Lv.w * EPSF);
#pragma unroll
        for (int p = 0; p < 64; p++) {
            float4 u = *(const float4*)(g_upart + ((size_t)(p * 1024) + b * 32 + ih) * 256 + s4 * 4);
            a.x += u.x; a.y += u.y; a.z += u.z; a.w += u.w;
        }
        float iv = inv_s[ih];
        a.x *= iv; a.y *= iv; a.z *= iv; a.w *= iv;
        *(float4*)&ss[ih][s4 * 4] = a;
    }

    float acc[4] = {0.f, 0.f, 0.f, 0.f};
    for (int cc = 0; cc < 16; cc++) {
        int c0 = cc * 16;
        __syncthreads();
#pragma unroll
        for (int q = 0; q < 8; q++) {
            int idx = t + 256 * q;
            int hh = idx >> 9, dd = (idx >> 4) & 31, c = idx & 15;
            Wvs[hh][dd][c] = Wv[(size_t)(hh * 64 + dbase + dd) * 256 + c0 + c];
        }
        __syncthreads();
#pragma unroll
        for (int c4 = 0; c4 < 4; c4++) {
            float4 sv = *(const float4*)&ss[ihx][c0 + c4 * 4];
#pragma unroll
            for (int k = 0; k < 4; k++) {
                const float* w = &Wvs[h][dq + k][c4 * 4];
                acc[k] += sv.x * w[0] + sv.y * w[1] + sv.z * w[2] + sv.w * w[3];
            }
        }
    }
#pragma unroll
    for (int k = 0; k < 4; k++)
        g_upd[(size_t)(b * 8 + i) * 256 + h * 64 + dbase + dq + k] = acc[k];
}

// ---------------- combined GRU gate GEMMs ----------------
__global__ void __launch_bounds__(256)
k_gates(const float* __restrict__ W_ih, const float* __restrict__ W_hh,
        const float* __restrict__ b_ih, const float* __restrict__ b_hh) {
    int mode = blockIdx.z;
    const float* A    = mode ? g_fill : g_upd;
    const float* W    = mode ? W_hh : W_ih;
    const float* bias = mode ? b_hh : b_ih;
    float* C = g_gates + mode * 196608;

    __shared__ float As[64][17];
    __shared__ float Bsx[64][17];
    int t = threadIdx.x;
    int row0 = blockIdx.x * 64, col0 = blockIdx.y * 64;
    int tx = t & 15, ty = t >> 4;

    float acc[4][4];
#pragma unroll
    for (int i = 0; i < 4; i++)
#pragma unroll
        for (int j = 0; j < 4; j++) acc[i][j] = 0.f;

    for (int k0 = 0; k0 < 256; k0 += 16) {
        __syncthreads();
        {
            int row = t >> 2, kp = t & 3;
            float4 a4 = *(const float4*)(A + (size_t)(row0 + row) * 256 + k0 + kp * 4);
            As[row][kp * 4 + 0] = a4.x; As[row][kp * 4 + 1] = a4.y;
            As[row][kp * 4 + 2] = a4.z; As[row][kp * 4 + 3] = a4.w;
            float4 b4 = *(const float4*)(W + (size_t)(col0 + row) * 256 + k0 + kp * 4);
            Bsx[row][kp * 4 + 0] = b4.x; Bsx[row][kp * 4 + 1] = b4.y;
            Bsx[row][kp * 4 + 2] = b4.z; Bsx[row][kp * 4 + 3] = b4.w;
        }
        __syncthreads();
#pragma unroll
        for (int kk = 0; kk < 16; kk++) {
            float a[4], bb[4];
#pragma unroll
            for (int i = 0; i < 4; i++) a[i]  = As[ty + 16 * i][kk];
#pragma unroll
            for (int j = 0; j < 4; j++) bb[j] = Bsx[tx + 16 * j][kk];
#pragma unroll
            for (int i = 0; i < 4; i++)
#pragma unroll
                for (int j = 0; j < 4; j++) acc[i][j] += a[i] * bb[j];
        }
    }
#pragma unroll
    for (int i = 0; i < 4; i++)
#pragma unroll
        for (int j = 0; j < 4; j++)
            C[(size_t)(row0 + ty + 16 * i) * 768 + col0 + tx + 16 * j] =
                acc[i][j] + bias[col0 + tx + 16 * j];
}

// ---------------- GRU elementwise ----------------
__global__ void k_gru() {
    int idx = blockIdx.x * blockDim.x + threadIdx.x;
    int r = idx >> 8, c = idx & 255;
    const float* gi = g_gates + (size_t)r * 768;
    const float* gh = g_gates + 196608 + (size_t)r * 768;
    float ir = gi[c], iz = gi[c + 256], in = gi[c + 512];
    float hr = gh[c], hz = gh[c + 256], hn = gh[c + 512];
    float rr = 1.f / (1.f + expf(-(ir + hr)));
    float zz = 1.f / (1.f + expf(-(iz + hz)));
    float nn = tanhf(in + rr * hn);
    float hp = g_fill[idx];
    g_fill[idx] = (1.f - zz) * nn + zz * hp;
}

__global__ void k_copyout(float* __restrict__ dst) {
    int idx = blockIdx.x * blockDim.x + threadIdx.x;
    dst[idx] = g_fill[idx];
}

// ---------------- launcher ----------------
extern "C" void kernel_launch(void* const* d_in, const int* in_sizes, int n_in,
                              void* d_out, int out_size) {
    const float* inputs = (const float*)d_in[0];
    const float* cond   = (const float*)d_in[1];
    const float* Wq     = (const float*)d_in[2];
    const float* Wk     = (const float*)d_in[3];
    const float* Wv     = (const float*)d_in[4];
    const float* W_ih   = (const float*)d_in[5];
    const float* W_hh   = (const float*)d_in[6];
    const float* b_ih   = (const float*)d_in[7];
    const float* b_hh   = (const float*)d_in[8];
    const float* lig    = (const float*)d_in[9];
    const float* lib    = (const float*)d_in[10];
    const float* lfg    = (const float*)d_in[11];
    const float* lfb    = (const float*)d_in[12];
    float* out = (float*)d_out;

    const int FUSED_SMEM = (64 * 260 + 32 * 68 + 32 * 256) * 4;   // 108,032 B
    cudaFuncSetAttribute(k_fused, cudaFuncAttributeMaxDynamicSharedMemorySize, FUSED_SMEM);

    k_rowstats<<<16384, 256>>>(inputs);                         // 1
    k_lnx<<<dim3(32, 32), 256>>>(inputs, lig, lib);             // 2
    k_pcomp<<<dim3(4, 4, 4), 256>>>(Wq, Wk);                    // 3

    for (int it = 0; it < 3; it++) {
        k_lnfill<<<32, 256>>>(lfg, lfb, cond, it == 0);         // 4
        k_tgemm<<<dim3(32, 4), 256>>>();                        // 5
        k_fused<<<dim3(32, 64), 256, FUSED_SMEM>>>(it == 2 ? 1 : 0, out + 65536);  // 6
        k_updproj<<<dim3(32, 2), 256>>>(Wv);                    // 7
        k_gates<<<dim3(4, 12, 2), 256>>>(W_ih, W_hh, b_ih, b_hh); // 8
        k_gru<<<256, 256>>>();                                  // 9
    }
    k_copyout<<<64, 1024>>>(out);
}

// round 14
// speedup vs baseline: 1.2360x; 1.2360x over previous
#include <cuda_runtime.h>
#include <cstdint>
#include <math.h>

#define SCALEF 0.125f     // DH^-0.5
#define EPSF   1e-8f
#define LNEPS  1e-5f

// -------- scratch (device globals: allocation-free) --------
__device__ float g_lnx[33554432];         // LN(inputs) [b][j][256]
__device__ float g_Lpart[32 * 8192];      // per-jc column-sum partials
__device__ float g_L[8192];               // L[b][c] = sum_j lnx
__device__ float g_P[4 * 256 * 256];      // P_h = Wq_h^T Wk_h
__device__ float g_t[1024 * 256];         // t[(b,ih)][c] (SCALE folded)
__device__ float g_upart[32 * 1024 * 256];// u partials [js][(b,ih)][c]
__device__ float g_rowsum[1024];          // [b][ih]
__device__ float g_fill[65536];           // fillers
__device__ float g_f[65536];              // LN(fillers)
__device__ float g_upd[65536];            // updates
__device__ float g_gates[2 * 256 * 768];  // [gi|gh]

// ---------------- packed f32x2 helpers ----------------
__device__ __forceinline__ unsigned long long ffma2(unsigned long long a,
                                                    unsigned long long b,
                                                    unsigned long long c) {
    unsigned long long d;
    asm("fma.rn.f32x2 %0, %1, %2, %3;" : "=l"(d) : "l"(a), "l"(b), "l"(c));
    return d;
}
__device__ __forceinline__ unsigned long long bcast2(float x) {
    unsigned u = __float_as_uint(x);
    return ((unsigned long long)u << 32) | (unsigned long long)u;
}
__device__ __forceinline__ float lo2(unsigned long long v) { return __uint_as_float((unsigned)v); }
__device__ __forceinline__ float hi2(unsigned long long v) { return __uint_as_float((unsigned)(v >> 32)); }

// ---------------- fused row-stats + LN + column-sum partials ----------------
// grid (32 b, 32 jc of 128 rows), 256 threads (8 warps x 16 rows each).
__global__ void __launch_bounds__(256)
k_lnx2(const float* __restrict__ x, const float* __restrict__ g,
       const float* __restrict__ b) {
    __shared__ float csm[8][256];

    int bb = blockIdx.x, jc = blockIdx.y;
    int t = threadIdx.x;
    int w = t >> 5, lane = t & 31;
    int row0 = bb * 4096 + jc * 128 + w * 16;

    float gg[8], bv[8];
#pragma unroll
    for (int u = 0; u < 8; u++) {
        gg[u] = g[lane + 32 * u];
        bv[u] = b[lane + 32 * u];
    }

    float csum[8];
#pragma unroll
    for (int u = 0; u < 8; u++) csum[u] = 0.f;

    for (int r = 0; r < 16; r++) {
        int row = row0 + r;
        const float* xr = x + (size_t)row * 256;
        float v[8];
        float s = 0.f;
#pragma unroll
        for (int u = 0; u < 8; u++) { v[u] = xr[lane + 32 * u]; s += v[u]; }
#pragma unroll
        for (int o = 16; o > 0; o >>= 1) s += __shfl_xor_sync(0xffffffffu, s, o);
        float m = s * (1.f / 256.f);
        float ss = 0.f;
#pragma unroll
        for (int u = 0; u < 8; u++) { float d = v[u] - m; ss += d * d; }
#pragma unroll
        for (int o = 16; o > 0; o >>= 1) ss += __shfl_xor_sync(0xffffffffu, ss, o);
        float rstd = rsqrtf(ss * (1.f / 256.f) + LNEPS);
        float* lr = g_lnx + (size_t)row * 256;
#pragma unroll
        for (int u = 0; u < 8; u++) {
            float o2 = (v[u] - m) * rstd * gg[u] + bv[u];
            lr[lane + 32 * u] = o2;
            csum[u] += o2;
        }
    }
#pragma unroll
    for (int u = 0; u < 8; u++) csm[w][lane + 32 * u] = csum[u];
    __syncthreads();
    // column c = t: sum the 8 warps
    float tot = 0.f;
#pragma unroll
    for (int w2 = 0; w2 < 8; w2++) tot += csm[w2][t];
    g_Lpart[jc * 8192 + bb * 256 + t] = tot;
}

// ---------------- L = sum of partials ----------------
__global__ void k_lsum() {
    int b = blockIdx.x, t = threadIdx.x;
    float s = 0.f;
#pragma unroll 8
    for (int jc = 0; jc < 32; jc++) s += g_Lpart[jc * 8192 + b * 256 + t];
    g_L[b * 256 + t] = s;
}

// ---------------- P_h = Wq_h^T @ Wk_h (once) ----------------
__global__ void __launch_bounds__(256)
k_pcomp(const float* __restrict__ Wq, const float* __restrict__ Wk) {
    int h = blockIdx.x, et = blockIdx.y, ct = blockIdx.z;
    int e0 = et * 64, c0 = ct * 64;
    int t = threadIdx.x;
    int tx = t & 15, ty = t >> 4;

    __shared__ float Qs[64][65];
    __shared__ float Ks[64][65];
    int d = t >> 2, sg = (t & 3) * 16;
#pragma unroll
    for (int q = 0; q < 4; q++) {
        float4 vq = *(const float4*)(Wq + (size_t)(h * 64 + d) * 256 + e0 + sg + q * 4);
        Qs[d][sg + q * 4 + 0] = vq.x; Qs[d][sg + q * 4 + 1] = vq.y;
        Qs[d][sg + q * 4 + 2] = vq.z; Qs[d][sg + q * 4 + 3] = vq.w;
        float4 vk = *(const float4*)(Wk + (size_t)(h * 64 + d) * 256 + c0 + sg + q * 4);
        Ks[d][sg + q * 4 + 0] = vk.x; Ks[d][sg + q * 4 + 1] = vk.y;
        Ks[d][sg + q * 4 + 2] = vk.z; Ks[d][sg + q * 4 + 3] = vk.w;
    }
    __syncthreads();
    float acc[4][4];
#pragma unroll
    for (int i = 0; i < 4; i++)
#pragma unroll
        for (int j = 0; j < 4; j++) acc[i][j] = 0.f;
    for (int dd = 0; dd < 64; dd++) {
        float a[4], bb[4];
#pragma unroll
        for (int i = 0; i < 4; i++) a[i] = Qs[dd][ty + 16 * i];
#pragma unroll
        for (int j = 0; j < 4; j++) bb[j] = Ks[dd][tx + 16 * j];
#pragma unroll
        for (int i = 0; i < 4; i++)
#pragma unroll
            for (int j = 0; j < 4; j++) acc[i][j] += a[i] * bb[j];
    }
#pragma unroll
    for (int i = 0; i < 4; i++)
#pragma unroll
        for (int j = 0; j < 4; j++)
            g_P[(size_t)h * 65536 + (size_t)(e0 + ty + 16 * i) * 256 + c0 + tx + 16 * j] = acc[i][j];
}

// ---------------- LN(fillers) + zero rowsum (+copy cond on iter0) ----------
__global__ void k_lnfill(const float* __restrict__ g, const float* __restrict__ b,
                         const float* __restrict__ cond, int first) {
    int t = threadIdx.x;
    int gt = blockIdx.x * 256 + t;
    if (gt < 1024) g_rowsum[gt] = 0.f;

    int row  = blockIdx.x * 8 + (t >> 5);   // 256 rows
    int lane = t & 31;
    const float* r = (first ? cond : g_fill) + (size_t)row * 256;
    float v[8];
    float s = 0.f;
#pragma unroll
    for (int u = 0; u < 8; u++) { v[u] = r[lane + 32 * u]; s += v[u]; }
#pragma unroll
    for (int o = 16; o > 0; o >>= 1) s += __shfl_xor_sync(0xffffffffu, s, o);
    float m = s * (1.f / 256.f);
    float ss = 0.f;
#pragma unroll
    for (int u = 0; u < 8; u++) { float d = v[u] - m; ss += d * d; }
#pragma unroll
    for (int o = 16; o > 0; o >>= 1) ss += __shfl_xor_sync(0xffffffffu, ss, o);
    float rstd = rsqrtf(ss * (1.f / 256.f) + LNEPS);
#pragma unroll
    for (int u = 0; u < 8; u++) {
        int c = lane + 32 * u;
        if (first) g_fill[row * 256 + c] = v[u];
        g_f[row * 256 + c] = (v[u] - m) * rstd * g[c] + b[c];
    }
}

// ---------------- t = SCALE * f @ P_h ----------------
__global__ void __launch_bounds__(256)
k_tgemm() {
    int b = blockIdx.x, ct = blockIdx.y;
    int c0 = ct * 64;
    int t = threadIdx.x;
    int ihx = t >> 3, c8 = (t & 7) * 8;
    int h = ihx & 3, i = ihx >> 2;

    __shared__ float fs[2048];
    __shared__ __align__(16) float Ps[4][32][68];

#pragma unroll
    for (int q = 0; q < 8; q++) fs[t + 256 * q] = g_f[b * 2048 + t + 256 * q];

    unsigned long long acc[4] = {0ull, 0ull, 0ull, 0ull};

    for (int ec = 0; ec < 8; ec++) {
        int e0 = ec * 32;
        __syncthreads();
#pragma unroll
        for (int q = 0; q < 8; q++) {
            int idx = t + 256 * q;
            int hh = idx >> 9, e = (idx >> 4) & 31, sg = idx & 15;
            float4 v = *(const float4*)(g_P + (size_t)hh * 65536 +
                                        (size_t)(e0 + e) * 256 + c0 + sg * 4);
            *(float4*)&Ps[hh][e][sg * 4] = v;
        }
        __syncthreads();
#pragma unroll
        for (int e = 0; e < 32; e++) {
            unsigned long long a = bcast2(fs[i * 256 + e0 + e]);
            ulonglong2 p0 = *(const ulonglong2*)&Ps[h][e][c8];
            ulonglong2 p1 = *(const ulonglong2*)&Ps[h][e][c8 + 4];
            acc[0] = ffma2(a, p0.x, acc[0]);
            acc[1] = ffma2(a, p0.y, acc[1]);
            acc[2] = ffma2(a, p1.x, acc[2]);
            acc[3] = ffma2(a, p1.y, acc[3]);
        }
    }
    int row = b * 32 + ihx;
#pragma unroll
    for (int q = 0; q < 4; q++) {
        g_t[(size_t)row * 256 + c0 + c8 + 2 * q]     = SCALEF * lo2(acc[q]);
        g_t[(size_t)row * 256 + c0 + c8 + 2 * q + 1] = SCALEF * hi2(acc[q]);
    }
}

// ---------------- fused: dots + inverted softmax + u-accumulation ------------
// grid (32 b, 32 js of 128 j), 128 threads, 36.8KB static smem -> 6 blocks/SM.
// phase1: 8 ih x 4 j per thread; phase2: 8 ih x 8 c per thread.  (R11-proven)
__global__ void __launch_bounds__(128)
k_fused(int last, float* __restrict__ attn_out) {
    __shared__ __align__(16) float dsm[32 * 132];            // dots/attn [ih][j]
    __shared__ __align__(16) float Bs[16 * 260];             // lnx tile (both phases)
    __shared__ __align__(16) unsigned long long t2[32 * 16]; // a-operand (u64 bcast)

    int b = blockIdx.x, js = blockIdx.y;
    int t = threadIdx.x;
    int ihg = t >> 5;          // warp id: ih group of 8
    int lane = t & 31;         // phase1: 4-j group; phase2: 8-c group
    int j0 = js * 128;

    const float* lnxb = g_lnx + (size_t)b * 4096 * 256;

    unsigned long long acc1[8][2];
#pragma unroll
    for (int ii = 0; ii < 8; ii++) { acc1[ii][0] = 0ull; acc1[ii][1] = 0ull; }

    // ---------- phase 1: dots[ih][j] over c ----------
    for (int cc = 0; cc < 16; cc++) {
        int c0 = cc * 16;
        __syncthreads();
        {   // t2: 32 ih x 16 c
            int ih = t >> 2, cq = (t & 3) * 4;
            float4 v = *(const float4*)(g_t + (size_t)(b * 32 + ih) * 256 + c0 + cq);
            t2[ih * 16 + cq + 0] = bcast2(v.x);
            t2[ih * 16 + cq + 1] = bcast2(v.y);
            t2[ih * 16 + cq + 2] = bcast2(v.z);
            t2[ih * 16 + cq + 3] = bcast2(v.w);
        }
        // Bs as [c][j]: 16 c x 128 j (row stride 132)
#pragma unroll
        for (int q = 0; q < 4; q++) {
            int idx = t + 128 * q;
            int j = idx >> 2, f4 = (idx & 3) * 4;
            float4 v = *(const float4*)(lnxb + (size_t)(j0 + j) * 256 + c0 + f4);
            Bs[(f4 + 0) * 132 + j] = v.x;
            Bs[(f4 + 1) * 132 + j] = v.y;
            Bs[(f4 + 2) * 132 + j] = v.z;
            Bs[(f4 + 3) * 132 + j] = v.w;
        }
        __syncthreads();
#pragma unroll
        for (int c = 0; c < 16; c++) {
            ulonglong2 b0 = *(const ulonglong2*)&Bs[c * 132 + lane * 4];
#pragma unroll
            for (int ii = 0; ii < 8; ii++) {
                unsigned long long a = t2[(ihg * 8 + ii) * 16 + c];
                acc1[ii][0] = ffma2(a, b0.x, acc1[ii][0]);
                acc1[ii][1] = ffma2(a, b0.y, acc1[ii][1]);
            }
        }
    }
    __syncthreads();
#pragma unroll
    for (int ii = 0; ii < 8; ii++)
        *(float4*)&dsm[(ihg * 8 + ii) * 132 + lane * 4] = make_float4(
            lo2(acc1[ii][0]), hi2(acc1[ii][0]), lo2(acc1[ii][1]), hi2(acc1[ii][1]));
    __syncthreads();

    // ---------- softmax over 32 (slot,head) per column j = t ----------
    {
        int j = t;
        float vcol[32], mx = -1e30f;
#pragma unroll
        for (int ih = 0; ih < 32; ih++) { vcol[ih] = dsm[ih * 132 + j]; mx = fmaxf(mx, vcol[ih]); }
        float sum = 0.f;
#pragma unroll
        for (int ih = 0; ih < 32; ih++) { vcol[ih] = __expf(vcol[ih] - mx); sum += vcol[ih]; }
        float inv = 1.f / sum;
#pragma unroll
        for (int ih = 0; ih < 32; ih++) { vcol[ih] *= inv; dsm[ih * 132 + j] = vcol[ih]; }
        if (last) {
#pragma unroll
            for (int i = 0; i < 8; i++)
                attn_out[((size_t)b * 8 + i) * 4096 + j0 + j] =
                    0.25f * (vcol[4 * i] + vcol[4 * i + 1] + vcol[4 * i + 2] + vcol[4 * i + 3]);
        }
    }

    // ---------- phase 2: u[ih][c] += attn[ih][j] * lnx[j][c] ----------
    unsigned long long acc2[8][4];
#pragma unroll
    for (int ii = 0; ii < 8; ii++)
#pragma unroll
        for (int q = 0; q < 4; q++) acc2[ii][q] = 0ull;
    float rs = 0.f;

    for (int jt = 0; jt < 8; jt++) {
        int jb = jt * 16;
        __syncthreads();
        // Bs as [j][c]: 16 j x 256 c (row stride 260)
#pragma unroll
        for (int q = 0; q < 8; q++) {
            int idx = t + 128 * q;
            int r = idx >> 6, f4 = idx & 63;
            *(float4*)&Bs[r * 260 + f4 * 4] =
                *(const float4*)(lnxb + (size_t)(j0 + jb + r) * 256 + f4 * 4);
        }
        {   // A2 pack (reuse t2) + rowsum partial; thread's ih = t>>2
            int ih = t >> 2, jq = (t & 3) * 4;
#pragma unroll
            for (int k = 0; k < 4; k++) {
                float a = dsm[ih * 132 + jb + jq + k];
                rs += a;
                t2[ih * 16 + jq + k] = bcast2(a);
            }
        }
        __syncthreads();
#pragma unroll
        for (int j = 0; j < 16; j++) {
            ulonglong2 b0 = *(const ulonglong2*)&Bs[j * 260 + lane * 8];
            ulonglong2 b1 = *(const ulonglong2*)&Bs[j * 260 + lane * 8 + 4];
#pragma unroll
            for (int ii = 0; ii < 8; ii++) {
                unsigned long long a = t2[(ihg * 8 + ii) * 16 + j];
                acc2[ii][0] = ffma2(a, b0.x, acc2[ii][0]);
                acc2[ii][1] = ffma2(a, b0.y, acc2[ii][1]);
                acc2[ii][2] = ffma2(a, b1.x, acc2[ii][2]);
                acc2[ii][3] = ffma2(a, b1.y, acc2[ii][3]);
            }
        }
    }

    // u partials (slice js; overwrite, no zeroing)
#pragma unroll
    for (int ii = 0; ii < 8; ii++) {
        float* dst = g_upart + ((size_t)(js * 1024) + b * 32 + ihg * 8 + ii) * 256 + lane * 8;
        *(float4*)dst       = make_float4(lo2(acc2[ii][0]), hi2(acc2[ii][0]),
                                          lo2(acc2[ii][1]), hi2(acc2[ii][1]));
        *(float4*)(dst + 4) = make_float4(lo2(acc2[ii][2]), hi2(acc2[ii][2]),
                                          lo2(acc2[ii][3]), hi2(acc2[ii][3]));
    }
    // rowsum: 4 threads share one ih
    rs += __shfl_xor_sync(0xffffffffu, rs, 1);
    rs += __shfl_xor_sync(0xffffffffu, rs, 2);
    if ((t & 3) == 0) atomicAdd(&g_rowsum[b * 32 + (t >> 2)], rs);
}

// ---------------- upd = ((Σu + eps·L)/denom) @ Wv_h^T ----------------
__global__ void __launch_bounds__(256)
k_updproj(const float* __restrict__ Wv) {
    int b = blockIdx.x, dh2 = blockIdx.y;
    int t = threadIdx.x;
    int ihx = t >> 3, dq = (t & 7) * 4;
    int h = ihx & 3, i = ihx >> 2;
    int dbase = dh2 * 32;

    __shared__ __align__(16) float ss[32][256];
    __shared__ float Wvs[4][32][16];
    __shared__ float inv_s[32];

    if (t < 32) inv_s[t] = 1.f / (g_rowsum[b * 32 + t] + 4096.f * EPSF);
    __syncthreads();

#pragma unroll
    for (int q = 0; q < 8; q++) {
        int idx = t + 256 * q;
        int ih = idx >> 6, s4 = idx & 63;
        float4 Lv = *(const float4*)(g_L + b * 256 + s4 * 4);
        float4 a = make_float4(Lv.x * EPSF, Lv.y * EPSF, Lv.z * EPSF, Lv.w * EPSF);
#pragma unroll
        for (int p = 0; p < 32; p++) {
            float4 u = *(const float4*)(g_upart + ((size_t)(p * 1024) + b * 32 + ih) * 256 + s4 * 4);
            a.x += u.x; a.y += u.y; a.z += u.z; a.w += u.w;
        }
        float iv = inv_s[ih];
        a.x *= iv; a.y *= iv; a.z *= iv; a.w *= iv;
        *(float4*)&ss[ih][s4 * 4] = a;
    }

    float acc[4] = {0.f, 0.f, 0.f, 0.f};
    for (int cc = 0; cc < 16; cc++) {
        int c0 = cc * 16;
        __syncthreads();
#pragma unroll
        for (int q = 0; q < 8; q++) {
            int idx = t + 256 * q;
            int hh = idx >> 9, dd = (idx >> 4) & 31, c = idx & 15;
            Wvs[hh][dd][c] = Wv[(size_t)(hh * 64 + dbase + dd) * 256 + c0 + c];
        }
        __syncthreads();
#pragma unroll
        for (int c4 = 0; c4 < 4; c4++) {
            float4 sv = *(const float4*)&ss[ihx][c0 + c4 * 4];
#pragma unroll
            for (int k = 0; k < 4; k++) {
                const float* w = &Wvs[h][dq + k][c4 * 4];
                acc[k] += sv.x * w[0] + sv.y * w[1] + sv.z * w[2] + sv.w * w[3];
            }
        }
    }
#pragma unroll
    for (int k = 0; k < 4; k++)
        g_upd[(size_t)(b * 8 + i) * 256 + h * 64 + dbase + dq + k] = acc[k];
}

// ---------------- combined GRU gate GEMMs ----------------
__global__ void __launch_bounds__(256)
k_gates(const float* __restrict__ W_ih, const float* __restrict__ W_hh,
        const float* __restrict__ b_ih, const float* __restrict__ b_hh) {
    int mode = blockIdx.z;
    const float* A    = mode ? g_fill : g_upd;
    const float* W    = mode ? W_hh : W_ih;
    const float* bias = mode ? b_hh : b_ih;
    float* C = g_gates + mode * 196608;

    __shared__ float As[64][17];
    __shared__ float Bsx[64][17];
    int t = threadIdx.x;
    int row0 = blockIdx.x * 64, col0 = blockIdx.y * 64;
    int tx = t & 15, ty = t >> 4;

    float acc[4][4];
#pragma unroll
    for (int i = 0; i < 4; i++)
#pragma unroll
        for (int j = 0; j < 4; j++) acc[i][j] = 0.f;

    for (int k0 = 0; k0 < 256; k0 += 16) {
        __syncthreads();
        {
            int row = t >> 2, kp = t & 3;
            float4 a4 = *(const float4*)(A + (size_t)(row0 + row) * 256 + k0 + kp * 4);
            As[row][kp * 4 + 0] = a4.x; As[row][kp * 4 + 1] = a4.y;
            As[row][kp * 4 + 2] = a4.z; As[row][kp * 4 + 3] = a4.w;
            float4 b4 = *(const float4*)(W + (size_t)(col0 + row) * 256 + k0 + kp * 4);
            Bsx[row][kp * 4 + 0] = b4.x; Bsx[row][kp * 4 + 1] = b4.y;
            Bsx[row][kp * 4 + 2] = b4.z; Bsx[row][kp * 4 + 3] = b4.w;
        }
        __syncthreads();
#pragma unroll
        for (int kk = 0; kk < 16; kk++) {
            float a[4], bb[4];
#pragma unroll
            for (int i = 0; i < 4; i++) a[i]  = As[ty + 16 * i][kk];
#pragma unroll
            for (int j = 0; j < 4; j++) bb[j] = Bsx[tx + 16 * j][kk];
#pragma unroll
            for (int i = 0; i < 4; i++)
#pragma unroll
                for (int j = 0; j < 4; j++) acc[i][j] += a[i] * bb[j];
        }
    }
#pragma unroll
    for (int i = 0; i < 4; i++)
#pragma unroll
        for (int j = 0; j < 4; j++)
            C[(size_t)(row0 + ty + 16 * i) * 768 + col0 + tx + 16 * j] =
                acc[i][j] + bias[col0 + tx + 16 * j];
}

// ---------------- GRU elementwise ----------------
__global__ void k_gru() {
    int idx = blockIdx.x * blockDim.x + threadIdx.x;
    int r = idx >> 8, c = idx & 255;
    const float* gi = g_gates + (size_t)r * 768;
    const float* gh = g_gates + 196608 + (size_t)r * 768;
    float ir = gi[c], iz = gi[c + 256], in = gi[c + 512];
    float hr = gh[c], hz = gh[c + 256], hn = gh[c + 512];
    float rr = 1.f / (1.f + expf(-(ir + hr)));
    float zz = 1.f / (1.f + expf(-(iz + hz)));
    float nn = tanhf(in + rr * hn);
    float hp = g_fill[idx];
    g_fill[idx] = (1.f - zz) * nn + zz * hp;
}

__global__ void k_copyout(float* __restrict__ dst) {
    int idx = blockIdx.x * blockDim.x + threadIdx.x;
    dst[idx] = g_fill[idx];
}

// ---------------- launcher ----------------
extern "C" void kernel_launch(void* const* d_in, const int* in_sizes, int n_in,
                              void* d_out, int out_size) {
    const float* inputs = (const float*)d_in[0];
    const float* cond   = (const float*)d_in[1];
    const float* Wq     = (const float*)d_in[2];
    const float* Wk     = (const float*)d_in[3];
    const float* Wv     = (const float*)d_in[4];
    const float* W_ih   = (const float*)d_in[5];
    const float* W_hh   = (const float*)d_in[6];
    const float* b_ih   = (const float*)d_in[7];
    const float* b_hh   = (const float*)d_in[8];
    const float* lig    = (const float*)d_in[9];
    const float* lib    = (const float*)d_in[10];
    const float* lfg    = (const float*)d_in[11];
    const float* lfb    = (const float*)d_in[12];
    float* out = (float*)d_out;

    k_lnx2<<<dim3(32, 32), 256>>>(inputs, lig, lib);            // 1
    k_lsum<<<32, 256>>>();                                      // 2
    k_pcomp<<<dim3(4, 4, 4), 256>>>(Wq, Wk);                    // 3

    for (int it = 0; it < 3; it++) {
        k_lnfill<<<32, 256>>>(lfg, lfb, cond, it == 0);         // 4
        k_tgemm<<<dim3(32, 4), 256>>>();                        // 5
        k_fused<<<dim3(32, 32), 128>>>(it == 2 ? 1 : 0, out + 65536);  // 6
        k_updproj<<<dim3(32, 2), 256>>>(Wv);                    // 7
        k_gates<<<dim3(4, 12, 2), 256>>>(W_ih, W_hh, b_ih, b_hh); // 8
        k_gru<<<256, 256>>>();                                  // 9
    }
    k_copyout<<<64, 1024>>>(out);
}

// round 15
// speedup vs baseline: 1.2604x; 1.0197x over previous
#include <cuda_runtime.h>
#include <cstdint>
#include <math.h>

#define SCALEF 0.125f     // DH^-0.5
#define EPSF   1e-8f
#define LNEPS  1e-5f

// -------- scratch (device globals: allocation-free) --------
__device__ float g_lnx[33554432];         // LN(inputs) [b][j][256]
__device__ float g_Lpart[32 * 8192];      // per-jc column-sum partials
__device__ float g_L[8192];               // L[b][c] = sum_j lnx
__device__ float g_P[4 * 256 * 256];      // P_h = Wq_h^T Wk_h
__device__ float g_t[1024 * 256];         // t[(b,ih)][c] (SCALE folded)
__device__ float g_upart[32 * 1024 * 256];// u partials [js][(b,ih)][c]
__device__ float g_rowsum[1024];          // [b][ih]
__device__ float g_fill[65536];           // fillers
__device__ float g_f[65536];              // LN(fillers)
__device__ float g_upd[65536];            // updates
__device__ float g_gates[2 * 256 * 768];  // [gi|gh]

// ---------------- packed f32x2 helpers ----------------
__device__ __forceinline__ unsigned long long ffma2(unsigned long long a,
                                                    unsigned long long b,
                                                    unsigned long long c) {
    unsigned long long d;
    asm("fma.rn.f32x2 %0, %1, %2, %3;" : "=l"(d) : "l"(a), "l"(b), "l"(c));
    return d;
}
__device__ __forceinline__ unsigned long long bcast2(float x) {
    unsigned u = __float_as_uint(x);
    return ((unsigned long long)u << 32) | (unsigned long long)u;
}
__device__ __forceinline__ float lo2(unsigned long long v) { return __uint_as_float((unsigned)v); }
__device__ __forceinline__ float hi2(unsigned long long v) { return __uint_as_float((unsigned)(v >> 32)); }

// ---------------- fused row-stats + LN + column-sum partials ----------------
__global__ void __launch_bounds__(256)
k_lnx2(const float* __restrict__ x, const float* __restrict__ g,
       const float* __restrict__ b) {
    __shared__ float csm[8][256];

    int bb = blockIdx.x, jc = blockIdx.y;
    int t = threadIdx.x;
    int w = t >> 5, lane = t & 31;
    int row0 = bb * 4096 + jc * 128 + w * 16;

    float gg[8], bv[8];
#pragma unroll
    for (int u = 0; u < 8; u++) {
        gg[u] = g[lane + 32 * u];
        bv[u] = b[lane + 32 * u];
    }

    float csum[8];
#pragma unroll
    for (int u = 0; u < 8; u++) csum[u] = 0.f;

    for (int r = 0; r < 16; r++) {
        int row = row0 + r;
        const float* xr = x + (size_t)row * 256;
        float v[8];
        float s = 0.f;
#pragma unroll
        for (int u = 0; u < 8; u++) { v[u] = xr[lane + 32 * u]; s += v[u]; }
#pragma unroll
        for (int o = 16; o > 0; o >>= 1) s += __shfl_xor_sync(0xffffffffu, s, o);
        float m = s * (1.f / 256.f);
        float ss = 0.f;
#pragma unroll
        for (int u = 0; u < 8; u++) { float d = v[u] - m; ss += d * d; }
#pragma unroll
        for (int o = 16; o > 0; o >>= 1) ss += __shfl_xor_sync(0xffffffffu, ss, o);
        float rstd = rsqrtf(ss * (1.f / 256.f) + LNEPS);
        float* lr = g_lnx + (size_t)row * 256;
#pragma unroll
        for (int u = 0; u < 8; u++) {
            float o2 = (v[u] - m) * rstd * gg[u] + bv[u];
            lr[lane + 32 * u] = o2;
            csum[u] += o2;
        }
    }
#pragma unroll
    for (int u = 0; u < 8; u++) csm[w][lane + 32 * u] = csum[u];
    __syncthreads();
    float tot = 0.f;
#pragma unroll
    for (int w2 = 0; w2 < 8; w2++) tot += csm[w2][t];
    g_Lpart[jc * 8192 + bb * 256 + t] = tot;
}

// ---------------- L = sum of partials ----------------
__global__ void k_lsum() {
    int b = blockIdx.x, t = threadIdx.x;
    float s = 0.f;
#pragma unroll 8
    for (int jc = 0; jc < 32; jc++) s += g_Lpart[jc * 8192 + b * 256 + t];
    g_L[b * 256 + t] = s;
}

// ---------------- P_h = Wq_h^T @ Wk_h (once) ----------------
__global__ void __launch_bounds__(256)
k_pcomp(const float* __restrict__ Wq, const float* __restrict__ Wk) {
    int h = blockIdx.x, et = blockIdx.y, ct = blockIdx.z;
    int e0 = et * 64, c0 = ct * 64;
    int t = threadIdx.x;
    int tx = t & 15, ty = t >> 4;

    __shared__ float Qs[64][65];
    __shared__ float Ks[64][65];
    int d = t >> 2, sg = (t & 3) * 16;
#pragma unroll
    for (int q = 0; q < 4; q++) {
        float4 vq = *(const float4*)(Wq + (size_t)(h * 64 + d) * 256 + e0 + sg + q * 4);
        Qs[d][sg + q * 4 + 0] = vq.x; Qs[d][sg + q * 4 + 1] = vq.y;
        Qs[d][sg + q * 4 + 2] = vq.z; Qs[d][sg + q * 4 + 3] = vq.w;
        float4 vk = *(const float4*)(Wk + (size_t)(h * 64 + d) * 256 + c0 + sg + q * 4);
        Ks[d][sg + q * 4 + 0] = vk.x; Ks[d][sg + q * 4 + 1] = vk.y;
        Ks[d][sg + q * 4 + 2] = vk.z; Ks[d][sg + q * 4 + 3] = vk.w;
    }
    __syncthreads();
    float acc[4][4];
#pragma unroll
    for (int i = 0; i < 4; i++)
#pragma unroll
        for (int j = 0; j < 4; j++) acc[i][j] = 0.f;
    for (int dd = 0; dd < 64; dd++) {
        float a[4], bb[4];
#pragma unroll
        for (int i = 0; i < 4; i++) a[i] = Qs[dd][ty + 16 * i];
#pragma unroll
        for (int j = 0; j < 4; j++) bb[j] = Ks[dd][tx + 16 * j];
#pragma unroll
        for (int i = 0; i < 4; i++)
#pragma unroll
            for (int j = 0; j < 4; j++) acc[i][j] += a[i] * bb[j];
    }
#pragma unroll
    for (int i = 0; i < 4; i++)
#pragma unroll
        for (int j = 0; j < 4; j++)
            g_P[(size_t)h * 65536 + (size_t)(e0 + ty + 16 * i) * 256 + c0 + tx + 16 * j] = acc[i][j];
}

// ---------------- LN(fillers) + zero rowsum (+copy cond on iter0) ----------
__global__ void k_lnfill(const float* __restrict__ g, const float* __restrict__ b,
                         const float* __restrict__ cond, int first) {
    int t = threadIdx.x;
    int gt = blockIdx.x * 256 + t;
    if (gt < 1024) g_rowsum[gt] = 0.f;

    int row  = blockIdx.x * 8 + (t >> 5);   // 256 rows
    int lane = t & 31;
    const float* r = (first ? cond : g_fill) + (size_t)row * 256;
    float v[8];
    float s = 0.f;
#pragma unroll
    for (int u = 0; u < 8; u++) { v[u] = r[lane + 32 * u]; s += v[u]; }
#pragma unroll
    for (int o = 16; o > 0; o >>= 1) s += __shfl_xor_sync(0xffffffffu, s, o);
    float m = s * (1.f / 256.f);
    float ss = 0.f;
#pragma unroll
    for (int u = 0; u < 8; u++) { float d = v[u] - m; ss += d * d; }
#pragma unroll
    for (int o = 16; o > 0; o >>= 1) ss += __shfl_xor_sync(0xffffffffu, ss, o);
    float rstd = rsqrtf(ss * (1.f / 256.f) + LNEPS);
#pragma unroll
    for (int u = 0; u < 8; u++) {
        int c = lane + 32 * u;
        if (first) g_fill[row * 256 + c] = v[u];
        g_f[row * 256 + c] = (v[u] - m) * rstd * g[c] + b[c];
    }
}

// ---------------- t = SCALE * f @ P_h ----------------
__global__ void __launch_bounds__(256)
k_tgemm() {
    int b = blockIdx.x, ct = blockIdx.y;
    int c0 = ct * 64;
    int t = threadIdx.x;
    int ihx = t >> 3, c8 = (t & 7) * 8;
    int h = ihx & 3, i = ihx >> 2;

    __shared__ float fs[2048];
    __shared__ __align__(16) float Ps[4][32][68];

#pragma unroll
    for (int q = 0; q < 8; q++) fs[t + 256 * q] = g_f[b * 2048 + t + 256 * q];

    unsigned long long acc[4] = {0ull, 0ull, 0ull, 0ull};

    for (int ec = 0; ec < 8; ec++) {
        int e0 = ec * 32;
        __syncthreads();
#pragma unroll
        for (int q = 0; q < 8; q++) {
            int idx = t + 256 * q;
            int hh = idx >> 9, e = (idx >> 4) & 31, sg = idx & 15;
            float4 v = *(const float4*)(g_P + (size_t)hh * 65536 +
                                        (size_t)(e0 + e) * 256 + c0 + sg * 4);
            *(float4*)&Ps[hh][e][sg * 4] = v;
        }
        __syncthreads();
#pragma unroll
        for (int e = 0; e < 32; e++) {
            unsigned long long a = bcast2(fs[i * 256 + e0 + e]);
            ulonglong2 p0 = *(const ulonglong2*)&Ps[h][e][c8];
            ulonglong2 p1 = *(const ulonglong2*)&Ps[h][e][c8 + 4];
            acc[0] = ffma2(a, p0.x, acc[0]);
            acc[1] = ffma2(a, p0.y, acc[1]);
            acc[2] = ffma2(a, p1.x, acc[2]);
            acc[3] = ffma2(a, p1.y, acc[3]);
        }
    }
    int row = b * 32 + ihx;
#pragma unroll
    for (int q = 0; q < 4; q++) {
        g_t[(size_t)row * 256 + c0 + c8 + 2 * q]     = SCALEF * lo2(acc[q]);
        g_t[(size_t)row * 256 + c0 + c8 + 2 * q + 1] = SCALEF * hi2(acc[q]);
    }
}

// ---------------- fused: dots + inverted softmax + u-accumulation ------------
// grid (32 b, 32 js of 128 j), 128 threads, 36.8KB static smem -> 6 blocks/SM.
// Phase 1 is software-pipelined: next chunk's LDGs issue before compute.
__global__ void __launch_bounds__(128)
k_fused(int last, float* __restrict__ attn_out) {
    __shared__ __align__(16) float dsm[32 * 132];            // dots/attn [ih][j]
    __shared__ __align__(16) float Bs[16 * 260];             // lnx tile (both phases)
    __shared__ __align__(16) unsigned long long t2[32 * 16]; // a-operand (u64 bcast)

    int b = blockIdx.x, js = blockIdx.y;
    int t = threadIdx.x;
    int ihg = t >> 5;          // warp id: ih group of 8
    int lane = t & 31;         // phase1: 4-j group; phase2: 8-c group
    int j0 = js * 128;

    const float* lnxb = g_lnx + (size_t)b * 4096 * 256;

    unsigned long long acc1[8][2];
#pragma unroll
    for (int ii = 0; ii < 8; ii++) { acc1[ii][0] = 0ull; acc1[ii][1] = 0ull; }

    // per-thread load addresses (phase 1)
    int p1_ih = t >> 2, p1_cq = (t & 3) * 4;
    const float* p1_tsrc = g_t + (size_t)(b * 32 + p1_ih) * 256 + p1_cq;
    int p1_j[4], p1_f4[4];
#pragma unroll
    for (int q = 0; q < 4; q++) {
        int idx = t + 128 * q;
        p1_j[q]  = idx >> 2;
        p1_f4[q] = (idx & 3) * 4;
    }

    // ---------- phase 1 (pipelined): dots[ih][j] over c ----------
    float4 treg = *(const float4*)(p1_tsrc);
    float4 breg[4];
#pragma unroll
    for (int q = 0; q < 4; q++)
        breg[q] = *(const float4*)(lnxb + (size_t)(j0 + p1_j[q]) * 256 + p1_f4[q]);

    for (int cc = 0; cc < 16; cc++) {
        // store stage from regs
        t2[p1_ih * 16 + p1_cq + 0] = bcast2(treg.x);
        t2[p1_ih * 16 + p1_cq + 1] = bcast2(treg.y);
        t2[p1_ih * 16 + p1_cq + 2] = bcast2(treg.z);
        t2[p1_ih * 16 + p1_cq + 3] = bcast2(treg.w);
#pragma unroll
        for (int q = 0; q < 4; q++) {
            Bs[(p1_f4[q] + 0) * 132 + p1_j[q]] = breg[q].x;
            Bs[(p1_f4[q] + 1) * 132 + p1_j[q]] = breg[q].y;
            Bs[(p1_f4[q] + 2) * 132 + p1_j[q]] = breg[q].z;
            Bs[(p1_f4[q] + 3) * 132 + p1_j[q]] = breg[q].w;
        }
        __syncthreads();

        // prefetch next chunk (hidden under compute)
        if (cc < 15) {
            int c0n = (cc + 1) * 16;
            treg = *(const float4*)(p1_tsrc + c0n);
#pragma unroll
            for (int q = 0; q < 4; q++)
                breg[q] = *(const float4*)(lnxb + (size_t)(j0 + p1_j[q]) * 256 + c0n + p1_f4[q]);
        }

        // compute chunk cc
#pragma unroll
        for (int c = 0; c < 16; c++) {
            ulonglong2 b0 = *(const ulonglong2*)&Bs[c * 132 + lane * 4];
#pragma unroll
            for (int ii = 0; ii < 8; ii++) {
                unsigned long long a = t2[(ihg * 8 + ii) * 16 + c];
                acc1[ii][0] = ffma2(a, b0.x, acc1[ii][0]);
                acc1[ii][1] = ffma2(a, b0.y, acc1[ii][1]);
            }
        }
        __syncthreads();
    }
#pragma unroll
    for (int ii = 0; ii < 8; ii++)
        *(float4*)&dsm[(ihg * 8 + ii) * 132 + lane * 4] = make_float4(
            lo2(acc1[ii][0]), hi2(acc1[ii][0]), lo2(acc1[ii][1]), hi2(acc1[ii][1]));
    __syncthreads();

    // ---------- softmax over 32 (slot,head) per column j = t ----------
    {
        int j = t;
        float vcol[32], mx = -1e30f;
#pragma unroll
        for (int ih = 0; ih < 32; ih++) { vcol[ih] = dsm[ih * 132 + j]; mx = fmaxf(mx, vcol[ih]); }
        float sum = 0.f;
#pragma unroll
        for (int ih = 0; ih < 32; ih++) { vcol[ih] = __expf(vcol[ih] - mx); sum += vcol[ih]; }
        float inv = 1.f / sum;
#pragma unroll
        for (int ih = 0; ih < 32; ih++) { vcol[ih] *= inv; dsm[ih * 132 + j] = vcol[ih]; }
        if (last) {
#pragma unroll
            for (int i = 0; i < 8; i++)
                attn_out[((size_t)b * 8 + i) * 4096 + j0 + j] =
                    0.25f * (vcol[4 * i] + vcol[4 * i + 1] + vcol[4 * i + 2] + vcol[4 * i + 3]);
        }
    }

    // ---------- phase 2: u[ih][c] += attn[ih][j] * lnx[j][c] ----------
    unsigned long long acc2[8][4];
#pragma unroll
    for (int ii = 0; ii < 8; ii++)
#pragma unroll
        for (int q = 0; q < 4; q++) acc2[ii][q] = 0ull;
    float rs = 0.f;

    for (int jt = 0; jt < 8; jt++) {
        int jb = jt * 16;
        __syncthreads();
#pragma unroll
        for (int q = 0; q < 8; q++) {
            int idx = t + 128 * q;
            int r = idx >> 6, f4 = idx & 63;
            *(float4*)&Bs[r * 260 + f4 * 4] =
                *(const float4*)(lnxb + (size_t)(j0 + jb + r) * 256 + f4 * 4);
        }
        {   // A2 pack (reuse t2) + rowsum partial; thread's ih = t>>2
            int ih = t >> 2, jq = (t & 3) * 4;
#pragma unroll
            for (int k = 0; k < 4; k++) {
                float a = dsm[ih * 132 + jb + jq + k];
                rs += a;
                t2[ih * 16 + jq + k] = bcast2(a);
            }
        }
        __syncthreads();
#pragma unroll
        for (int j = 0; j < 16; j++) {
            ulonglong2 b0 = *(const ulonglong2*)&Bs[j * 260 + lane * 8];
            ulonglong2 b1 = *(const ulonglong2*)&Bs[j * 260 + lane * 8 + 4];
#pragma unroll
            for (int ii = 0; ii < 8; ii++) {
                unsigned long long a = t2[(ihg * 8 + ii) * 16 + j];
                acc2[ii][0] = ffma2(a, b0.x, acc2[ii][0]);
                acc2[ii][1] = ffma2(a, b0.y, acc2[ii][1]);
                acc2[ii][2] = ffma2(a, b1.x, acc2[ii][2]);
                acc2[ii][3] = ffma2(a, b1.y, acc2[ii][3]);
            }
        }
    }

    // u partials (slice js; overwrite, no zeroing)
#pragma unroll
    for (int ii = 0; ii < 8; ii++) {
        float* dst = g_upart + ((size_t)(js * 1024) + b * 32 + ihg * 8 + ii) * 256 + lane * 8;
        *(float4*)dst       = make_float4(lo2(acc2[ii][0]), hi2(acc2[ii][0]),
                                          lo2(acc2[ii][1]), hi2(acc2[ii][1]));
        *(float4*)(dst + 4) = make_float4(lo2(acc2[ii][2]), hi2(acc2[ii][2]),
                                          lo2(acc2[ii][3]), hi2(acc2[ii][3]));
    }
    // rowsum: 4 threads share one ih
    rs += __shfl_xor_sync(0xffffffffu, rs, 1);
    rs += __shfl_xor_sync(0xffffffffu, rs, 2);
    if ((t & 3) == 0) atomicAdd(&g_rowsum[b * 32 + (t >> 2)], rs);
}

// ---------------- upd = ((Σu + eps·L)/denom) @ Wv_h^T ----------------
__global__ void __launch_bounds__(256)
k_updproj(const float* __restrict__ Wv) {
    int b = blockIdx.x, dh2 = blockIdx.y;
    int t = threadIdx.x;
    int ihx = t >> 3, dq = (t & 7) * 4;
    int h = ihx & 3, i = ihx >> 2;
    int dbase = dh2 * 32;

    __shared__ __align__(16) float ss[32][256];
    __shared__ float Wvs[4][32][16];
    __shared__ float inv_s[32];

    if (t < 32) inv_s[t] = 1.f / (g_rowsum[b * 32 + t] + 4096.f * EPSF);
    __syncthreads();

#pragma unroll
    for (int q = 0; q < 8; q++) {
        int idx = t + 256 * q;
        int ih = idx >> 6, s4 = idx & 63;
        float4 Lv = *(const float4*)(g_L + b * 256 + s4 * 4);
        float4 a = make_float4(Lv.x * EPSF, Lv.y * EPSF, Lv.z * EPSF, Lv.w * EPSF);
#pragma unroll
        for (int p = 0; p < 32; p++) {
            float4 u = *(const float4*)(g_upart + ((size_t)(p * 1024) + b * 32 + ih) * 256 + s4 * 4);
            a.x += u.x; a.y += u.y; a.z += u.z; a.w += u.w;
        }
        float iv = inv_s[ih];
        a.x *= iv; a.y *= iv; a.z *= iv; a.w *= iv;
        *(float4*)&ss[ih][s4 * 4] = a;
    }

    float acc[4] = {0.f, 0.f, 0.f, 0.f};
    for (int cc = 0; cc < 16; cc++) {
        int c0 = cc * 16;
        __syncthreads();
#pragma unroll
        for (int q = 0; q < 8; q++) {
            int idx = t + 256 * q;
            int hh = idx >> 9, dd = (idx >> 4) & 31, c = idx & 15;
            Wvs[hh][dd][c] = Wv[(size_t)(hh * 64 + dbase + dd) * 256 + c0 + c];
        }
        __syncthreads();
#pragma unroll
        for (int c4 = 0; c4 < 4; c4++) {
            float4 sv = *(const float4*)&ss[ihx][c0 + c4 * 4];
#pragma unroll
            for (int k = 0; k < 4; k++) {
                const float* w = &Wvs[h][dq + k][c4 * 4];
                acc[k] += sv.x * w[0] + sv.y * w[1] + sv.z * w[2] + sv.w * w[3];
            }
        }
    }
#pragma unroll
    for (int k = 0; k < 4; k++)
        g_upd[(size_t)(b * 8 + i) * 256 + h * 64 + dbase + dq + k] = acc[k];
}

// ---------------- combined GRU gate GEMMs ----------------
__global__ void __launch_bounds__(256)
k_gates(const float* __restrict__ W_ih, const float* __restrict__ W_hh,
        const float* __restrict__ b_ih, const float* __restrict__ b_hh) {
    int mode = blockIdx.z;
    const float* A    = mode ? g_fill : g_upd;
    const float* W    = mode ? W_hh : W_ih;
    const float* bias = mode ? b_hh : b_ih;
    float* C = g_gates + mode * 196608;

    __shared__ float As[64][17];
    __shared__ float Bsx[64][17];
    int t = threadIdx.x;
    int row0 = blockIdx.x * 64, col0 = blockIdx.y * 64;
    int tx = t & 15, ty = t >> 4;

    float acc[4][4];
#pragma unroll
    for (int i = 0; i < 4; i++)
#pragma unroll
        for (int j = 0; j < 4; j++) acc[i][j] = 0.f;

    for (int k0 = 0; k0 < 256; k0 += 16) {
        __syncthreads();
        {
            int row = t >> 2, kp = t & 3;
            float4 a4 = *(const float4*)(A + (size_t)(row0 + row) * 256 + k0 + kp * 4);
            As[row][kp * 4 + 0] = a4.x; As[row][kp * 4 + 1] = a4.y;
            As[row][kp * 4 + 2] = a4.z; As[row][kp * 4 + 3] = a4.w;
            float4 b4 = *(const float4*)(W + (size_t)(col0 + row) * 256 + k0 + kp * 4);
            Bsx[row][kp * 4 + 0] = b4.x; Bsx[row][kp * 4 + 1] = b4.y;
            Bsx[row][kp * 4 + 2] = b4.z; Bsx[row][kp * 4 + 3] = b4.w;
        }
        __syncthreads();
#pragma unroll
        for (int kk = 0; kk < 16; kk++) {
            float a[4], bb[4];
#pragma unroll
            for (int i = 0; i < 4; i++) a[i]  = As[ty + 16 * i][kk];
#pragma unroll
            for (int j = 0; j < 4; j++) bb[j] = Bsx[tx + 16 * j][kk];
#pragma unroll
            for (int i = 0; i < 4; i++)
#pragma unroll
                for (int j = 0; j < 4; j++) acc[i][j] += a[i] * bb[j];
        }
    }
#pragma unroll
    for (int i = 0; i < 4; i++)
#pragma unroll
        for (int j = 0; j < 4; j++)
            C[(size_t)(row0 + ty + 16 * i) * 768 + col0 + tx + 16 * j] =
                acc[i][j] + bias[col0 + tx + 16 * j];
}

// ---------------- GRU elementwise ----------------
__global__ void k_gru() {
    int idx = blockIdx.x * blockDim.x + threadIdx.x;
    int r = idx >> 8, c = idx & 255;
    const float* gi = g_gates + (size_t)r * 768;
    const float* gh = g_gates + 196608 + (size_t)r * 768;
    float ir = gi[c], iz = gi[c + 256], in = gi[c + 512];
    float hr = gh[c], hz = gh[c + 256], hn = gh[c + 512];
    float rr = 1.f / (1.f + expf(-(ir + hr)));
    float zz = 1.f / (1.f + expf(-(iz + hz)));
    float nn = tanhf(in + rr * hn);
    float hp = g_fill[idx];
    g_fill[idx] = (1.f - zz) * nn + zz * hp;
}

__global__ void k_copyout(float* __restrict__ dst) {
    int idx = blockIdx.x * blockDim.x + threadIdx.x;
    dst[idx] = g_fill[idx];
}

// ---------------- launcher ----------------
extern "C" void kernel_launch(void* const* d_in, const int* in_sizes, int n_in,
                              void* d_out, int out_size) {
    const float* inputs = (const float*)d_in[0];
    const float* cond   = (const float*)d_in[1];
    const float* Wq     = (const float*)d_in[2];
    const float* Wk     = (const float*)d_in[3];
    const float* Wv     = (const float*)d_in[4];
    const float* W_ih   = (const float*)d_in[5];
    const float* W_hh   = (const float*)d_in[6];
    const float* b_ih   = (const float*)d_in[7];
    const float* b_hh   = (const float*)d_in[8];
    const float* lig    = (const float*)d_in[9];
    const float* lib    = (const float*)d_in[10];
    const float* lfg    = (const float*)d_in[11];
    const float* lfb    = (const float*)d_in[12];
    float* out = (float*)d_out;

    k_lnx2<<<dim3(32, 32), 256>>>(inputs, lig, lib);            // 1
    k_lsum<<<32, 256>>>();                                      // 2
    k_pcomp<<<dim3(4, 4, 4), 256>>>(Wq, Wk);                    // 3

    for (int it = 0; it < 3; it++) {
        k_lnfill<<<32, 256>>>(lfg, lfb, cond, it == 0);         // 4
        k_tgemm<<<dim3(32, 4), 256>>>();                        // 5
        k_fused<<<dim3(32, 32), 128>>>(it == 2 ? 1 : 0, out + 65536);  // 6
        k_updproj<<<dim3(32, 2), 256>>>(Wv);                    // 7
        k_gates<<<dim3(4, 12, 2), 256>>>(W_ih, W_hh, b_ih, b_hh); // 8
        k_gru<<<256, 256>>>();                                  // 9
    }
    k_copyout<<<64, 1024>>>(out);
}

// round 16
// speedup vs baseline: 1.2608x; 1.0004x over previous
#include <cuda_runtime.h>
#include <cstdint>
#include <math.h>

#define SCALEF 0.125f     // DH^-0.5
#define EPSF   1e-8f
#define LNEPS  1e-5f

// -------- scratch (device globals: allocation-free) --------
__device__ float g_lnx[33554432];         // LN(inputs) [b][j][256]
__device__ float g_Lpart[32 * 8192];      // per-jc column-sum partials
__device__ float g_L[8192];               // L[b][c] = sum_j lnx
__device__ float g_P[4 * 256 * 256];      // P_h = Wq_h^T Wk_h
__device__ float g_t[1024 * 256];         // t[(b,ih)][c] (SCALE folded)
__device__ float g_upart[32 * 1024 * 256];// u partials [js][(b,ih)][c]
__device__ float g_rowsum[1024];          // [b][ih]
__device__ float g_fill[65536];           // fillers
__device__ float g_f[65536];              // LN(fillers)
__device__ float g_upd[65536];            // updates
__device__ float g_gates[2 * 256 * 768];  // [gi|gh]

// ---------------- packed f32x2 helpers ----------------
__device__ __forceinline__ unsigned long long ffma2(unsigned long long a,
                                                    unsigned long long b,
                                                    unsigned long long c) {
    unsigned long long d;
    asm("fma.rn.f32x2 %0, %1, %2, %3;" : "=l"(d) : "l"(a), "l"(b), "l"(c));
    return d;
}
__device__ __forceinline__ unsigned long long bcast2(float x) {
    unsigned u = __float_as_uint(x);
    return ((unsigned long long)u << 32) | (unsigned long long)u;
}
__device__ __forceinline__ float lo2(unsigned long long v) { return __uint_as_float((unsigned)v); }
__device__ __forceinline__ float hi2(unsigned long long v) { return __uint_as_float((unsigned)(v >> 32)); }

// ---------------- fused row-stats + LN + column-sum partials ----------------
__global__ void __launch_bounds__(256)
k_lnx2(const float* __restrict__ x, const float* __restrict__ g,
       const float* __restrict__ b) {
    __shared__ float csm[8][256];

    int bb = blockIdx.x, jc = blockIdx.y;
    int t = threadIdx.x;
    int w = t >> 5, lane = t & 31;
    int row0 = bb * 4096 + jc * 128 + w * 16;

    float gg[8], bv[8];
#pragma unroll
    for (int u = 0; u < 8; u++) {
        gg[u] = g[lane + 32 * u];
        bv[u] = b[lane + 32 * u];
    }

    float csum[8];
#pragma unroll
    for (int u = 0; u < 8; u++) csum[u] = 0.f;

    for (int r = 0; r < 16; r++) {
        int row = row0 + r;
        const float* xr = x + (size_t)row * 256;
        float v[8];
        float s = 0.f;
#pragma unroll
        for (int u = 0; u < 8; u++) { v[u] = xr[lane + 32 * u]; s += v[u]; }
#pragma unroll
        for (int o = 16; o > 0; o >>= 1) s += __shfl_xor_sync(0xffffffffu, s, o);
        float m = s * (1.f / 256.f);
        float ss = 0.f;
#pragma unroll
        for (int u = 0; u < 8; u++) { float d = v[u] - m; ss += d * d; }
#pragma unroll
        for (int o = 16; o > 0; o >>= 1) ss += __shfl_xor_sync(0xffffffffu, ss, o);
        float rstd = rsqrtf(ss * (1.f / 256.f) + LNEPS);
        float* lr = g_lnx + (size_t)row * 256;
#pragma unroll
        for (int u = 0; u < 8; u++) {
            float o2 = (v[u] - m) * rstd * gg[u] + bv[u];
            lr[lane + 32 * u] = o2;
            csum[u] += o2;
        }
    }
#pragma unroll
    for (int u = 0; u < 8; u++) csm[w][lane + 32 * u] = csum[u];
    __syncthreads();
    float tot = 0.f;
#pragma unroll
    for (int w2 = 0; w2 < 8; w2++) tot += csm[w2][t];
    g_Lpart[jc * 8192 + bb * 256 + t] = tot;
}

// ---------------- L = sum of partials ----------------
__global__ void k_lsum() {
    int b = blockIdx.x, t = threadIdx.x;
    float s = 0.f;
#pragma unroll 8
    for (int jc = 0; jc < 32; jc++) s += g_Lpart[jc * 8192 + b * 256 + t];
    g_L[b * 256 + t] = s;
}

// ---------------- P_h = Wq_h^T @ Wk_h (once) ----------------
__global__ void __launch_bounds__(256)
k_pcomp(const float* __restrict__ Wq, const float* __restrict__ Wk) {
    int h = blockIdx.x, et = blockIdx.y, ct = blockIdx.z;
    int e0 = et * 64, c0 = ct * 64;
    int t = threadIdx.x;
    int tx = t & 15, ty = t >> 4;

    __shared__ float Qs[64][65];
    __shared__ float Ks[64][65];
    int d = t >> 2, sg = (t & 3) * 16;
#pragma unroll
    for (int q = 0; q < 4; q++) {
        float4 vq = *(const float4*)(Wq + (size_t)(h * 64 + d) * 256 + e0 + sg + q * 4);
        Qs[d][sg + q * 4 + 0] = vq.x; Qs[d][sg + q * 4 + 1] = vq.y;
        Qs[d][sg + q * 4 + 2] = vq.z; Qs[d][sg + q * 4 + 3] = vq.w;
        float4 vk = *(const float4*)(Wk + (size_t)(h * 64 + d) * 256 + c0 + sg + q * 4);
        Ks[d][sg + q * 4 + 0] = vk.x; Ks[d][sg + q * 4 + 1] = vk.y;
        Ks[d][sg + q * 4 + 2] = vk.z; Ks[d][sg + q * 4 + 3] = vk.w;
    }
    __syncthreads();
    float acc[4][4];
#pragma unroll
    for (int i = 0; i < 4; i++)
#pragma unroll
        for (int j = 0; j < 4; j++) acc[i][j] = 0.f;
    for (int dd = 0; dd < 64; dd++) {
        float a[4], bb[4];
#pragma unroll
        for (int i = 0; i < 4; i++) a[i] = Qs[dd][ty + 16 * i];
#pragma unroll
        for (int j = 0; j < 4; j++) bb[j] = Ks[dd][tx + 16 * j];
#pragma unroll
        for (int i = 0; i < 4; i++)
#pragma unroll
            for (int j = 0; j < 4; j++) acc[i][j] += a[i] * bb[j];
    }
#pragma unroll
    for (int i = 0; i < 4; i++)
#pragma unroll
        for (int j = 0; j < 4; j++)
            g_P[(size_t)h * 65536 + (size_t)(e0 + ty + 16 * i) * 256 + c0 + tx + 16 * j] = acc[i][j];
}

// ---------------- LN(fillers) + zero rowsum (+copy cond on iter0) ----------
__global__ void k_lnfill(const float* __restrict__ g, const float* __restrict__ b,
                         const float* __restrict__ cond, int first) {
    int t = threadIdx.x;
    int gt = blockIdx.x * 256 + t;
    if (gt < 1024) g_rowsum[gt] = 0.f;

    int row  = blockIdx.x * 8 + (t >> 5);   // 256 rows
    int lane = t & 31;
    const float* r = (first ? cond : g_fill) + (size_t)row * 256;
    float v[8];
    float s = 0.f;
#pragma unroll
    for (int u = 0; u < 8; u++) { v[u] = r[lane + 32 * u]; s += v[u]; }
#pragma unroll
    for (int o = 16; o > 0; o >>= 1) s += __shfl_xor_sync(0xffffffffu, s, o);
    float m = s * (1.f / 256.f);
    float ss = 0.f;
#pragma unroll
    for (int u = 0; u < 8; u++) { float d = v[u] - m; ss += d * d; }
#pragma unroll
    for (int o = 16; o > 0; o >>= 1) ss += __shfl_xor_sync(0xffffffffu, ss, o);
    float rstd = rsqrtf(ss * (1.f / 256.f) + LNEPS);
#pragma unroll
    for (int u = 0; u < 8; u++) {
        int c = lane + 32 * u;
        if (first) g_fill[row * 256 + c] = v[u];
        g_f[row * 256 + c] = (v[u] - m) * rstd * g[c] + b[c];
    }
}

// ---------------- t = SCALE * f @ P_h ----------------
__global__ void __launch_bounds__(256)
k_tgemm() {
    int b = blockIdx.x, ct = blockIdx.y;
    int c0 = ct * 64;
    int t = threadIdx.x;
    int ihx = t >> 3, c8 = (t & 7) * 8;
    int h = ihx & 3, i = ihx >> 2;

    __shared__ float fs[2048];
    __shared__ __align__(16) float Ps[4][32][68];

#pragma unroll
    for (int q = 0; q < 8; q++) fs[t + 256 * q] = g_f[b * 2048 + t + 256 * q];

    unsigned long long acc[4] = {0ull, 0ull, 0ull, 0ull};

    for (int ec = 0; ec < 8; ec++) {
        int e0 = ec * 32;
        __syncthreads();
#pragma unroll
        for (int q = 0; q < 8; q++) {
            int idx = t + 256 * q;
            int hh = idx >> 9, e = (idx >> 4) & 31, sg = idx & 15;
            float4 v = *(const float4*)(g_P + (size_t)hh * 65536 +
                                        (size_t)(e0 + e) * 256 + c0 + sg * 4);
            *(float4*)&Ps[hh][e][sg * 4] = v;
        }
        __syncthreads();
#pragma unroll
        for (int e = 0; e < 32; e++) {
            unsigned long long a = bcast2(fs[i * 256 + e0 + e]);
            ulonglong2 p0 = *(const ulonglong2*)&Ps[h][e][c8];
            ulonglong2 p1 = *(const ulonglong2*)&Ps[h][e][c8 + 4];
            acc[0] = ffma2(a, p0.x, acc[0]);
            acc[1] = ffma2(a, p0.y, acc[1]);
            acc[2] = ffma2(a, p1.x, acc[2]);
            acc[3] = ffma2(a, p1.y, acc[3]);
        }
    }
    int row = b * 32 + ihx;
#pragma unroll
    for (int q = 0; q < 4; q++) {
        g_t[(size_t)row * 256 + c0 + c8 + 2 * q]     = SCALEF * lo2(acc[q]);
        g_t[(size_t)row * 256 + c0 + c8 + 2 * q + 1] = SCALEF * hi2(acc[q]);
    }
}

// ---------------- fused: dots + inverted softmax + u-accumulation ------------
// grid (32 b, 32 js of 128 j), 128 threads, 36.8KB static smem -> 6 blocks/SM.
// Phase 1 is software-pipelined: next chunk's LDGs issue before compute.
__global__ void __launch_bounds__(128)
k_fused(int last, float* __restrict__ attn_out) {
    __shared__ __align__(16) float dsm[32 * 132];            // dots/attn [ih][j]
    __shared__ __align__(16) float Bs[16 * 260];             // lnx tile (both phases)
    __shared__ __align__(16) unsigned long long t2[32 * 16]; // a-operand (u64 bcast)

    int b = blockIdx.x, js = blockIdx.y;
    int t = threadIdx.x;
    int ihg = t >> 5;          // warp id: ih group of 8
    int lane = t & 31;         // phase1: 4-j group; phase2: 8-c group
    int j0 = js * 128;

    const float* lnxb = g_lnx + (size_t)b * 4096 * 256;

    unsigned long long acc1[8][2];
#pragma unroll
    for (int ii = 0; ii < 8; ii++) { acc1[ii][0] = 0ull; acc1[ii][1] = 0ull; }

    // per-thread load addresses (phase 1)
    int p1_ih = t >> 2, p1_cq = (t & 3) * 4;
    const float* p1_tsrc = g_t + (size_t)(b * 32 + p1_ih) * 256 + p1_cq;
    int p1_j[4], p1_f4[4];
#pragma unroll
    for (int q = 0; q < 4; q++) {
        int idx = t + 128 * q;
        p1_j[q]  = idx >> 2;
        p1_f4[q] = (idx & 3) * 4;
    }

    // ---------- phase 1 (pipelined): dots[ih][j] over c ----------
    float4 treg = *(const float4*)(p1_tsrc);
    float4 breg[4];
#pragma unroll
    for (int q = 0; q < 4; q++)
        breg[q] = *(const float4*)(lnxb + (size_t)(j0 + p1_j[q]) * 256 + p1_f4[q]);

    for (int cc = 0; cc < 16; cc++) {
        // store stage from regs
        t2[p1_ih * 16 + p1_cq + 0] = bcast2(treg.x);
        t2[p1_ih * 16 + p1_cq + 1] = bcast2(treg.y);
        t2[p1_ih * 16 + p1_cq + 2] = bcast2(treg.z);
        t2[p1_ih * 16 + p1_cq + 3] = bcast2(treg.w);
#pragma unroll
        for (int q = 0; q < 4; q++) {
            Bs[(p1_f4[q] + 0) * 132 + p1_j[q]] = breg[q].x;
            Bs[(p1_f4[q] + 1) * 132 + p1_j[q]] = breg[q].y;
            Bs[(p1_f4[q] + 2) * 132 + p1_j[q]] = breg[q].z;
            Bs[(p1_f4[q] + 3) * 132 + p1_j[q]] = breg[q].w;
        }
        __syncthreads();

        // prefetch next chunk (hidden under compute)
        if (cc < 15) {
            int c0n = (cc + 1) * 16;
            treg = *(const float4*)(p1_tsrc + c0n);
#pragma unroll
            for (int q = 0; q < 4; q++)
                breg[q] = *(const float4*)(lnxb + (size_t)(j0 + p1_j[q]) * 256 + c0n + p1_f4[q]);
        }

        // compute chunk cc
#pragma unroll
        for (int c = 0; c < 16; c++) {
            ulonglong2 b0 = *(const ulonglong2*)&Bs[c * 132 + lane * 4];
#pragma unroll
            for (int ii = 0; ii < 8; ii++) {
                unsigned long long a = t2[(ihg * 8 + ii) * 16 + c];
                acc1[ii][0] = ffma2(a, b0.x, acc1[ii][0]);
                acc1[ii][1] = ffma2(a, b0.y, acc1[ii][1]);
            }
        }
        __syncthreads();
    }
#pragma unroll
    for (int ii = 0; ii < 8; ii++)
        *(float4*)&dsm[(ihg * 8 + ii) * 132 + lane * 4] = make_float4(
            lo2(acc1[ii][0]), hi2(acc1[ii][0]), lo2(acc1[ii][1]), hi2(acc1[ii][1]));
    __syncthreads();

    // ---------- softmax over 32 (slot,head) per column j = t ----------
    {
        int j = t;
        float vcol[32], mx = -1e30f;
#pragma unroll
        for (int ih = 0; ih < 32; ih++) { vcol[ih] = dsm[ih * 132 + j]; mx = fmaxf(mx, vcol[ih]); }
        float sum = 0.f;
#pragma unroll
        for (int ih = 0; ih < 32; ih++) { vcol[ih] = __expf(vcol[ih] - mx); sum += vcol[ih]; }
        float inv = 1.f / sum;
#pragma unroll
        for (int ih = 0; ih < 32; ih++) { vcol[ih] *= inv; dsm[ih * 132 + j] = vcol[ih]; }
        if (last) {
#pragma unroll
            for (int i = 0; i < 8; i++)
                attn_out[((size_t)b * 8 + i) * 4096 + j0 + j] =
                    0.25f * (vcol[4 * i] + vcol[4 * i + 1] + vcol[4 * i + 2] + vcol[4 * i + 3]);
        }
    }

    // ---------- phase 2: u[ih][c] += attn[ih][j] * lnx[j][c] ----------
    unsigned long long acc2[8][4];
#pragma unroll
    for (int ii = 0; ii < 8; ii++)
#pragma unroll
        for (int q = 0; q < 4; q++) acc2[ii][q] = 0ull;
    float rs = 0.f;

    for (int jt = 0; jt < 8; jt++) {
        int jb = jt * 16;
        __syncthreads();
#pragma unroll
        for (int q = 0; q < 8; q++) {
            int idx = t + 128 * q;
            int r = idx >> 6, f4 = idx & 63;
            *(float4*)&Bs[r * 260 + f4 * 4] =
                *(const float4*)(lnxb + (size_t)(j0 + jb + r) * 256 + f4 * 4);
        }
        {   // A2 pack (reuse t2) + rowsum partial; thread's ih = t>>2
            int ih = t >> 2, jq = (t & 3) * 4;
#pragma unroll
            for (int k = 0; k < 4; k++) {
                float a = dsm[ih * 132 + jb + jq + k];
                rs += a;
                t2[ih * 16 + jq + k] = bcast2(a);
            }
        }
        __syncthreads();
#pragma unroll
        for (int j = 0; j < 16; j++) {
            ulonglong2 b0 = *(const ulonglong2*)&Bs[j * 260 + lane * 8];
            ulonglong2 b1 = *(const ulonglong2*)&Bs[j * 260 + lane * 8 + 4];
#pragma unroll
            for (int ii = 0; ii < 8; ii++) {
                unsigned long long a = t2[(ihg * 8 + ii) * 16 + j];
                acc2[ii][0] = ffma2(a, b0.x, acc2[ii][0]);
                acc2[ii][1] = ffma2(a, b0.y, acc2[ii][1]);
                acc2[ii][2] = ffma2(a, b1.x, acc2[ii][2]);
                acc2[ii][3] = ffma2(a, b1.y, acc2[ii][3]);
            }
        }
    }

    // u partials (slice js; overwrite, no zeroing)
#pragma unroll
    for (int ii = 0; ii < 8; ii++) {
        float* dst = g_upart + ((size_t)(js * 1024) + b * 32 + ihg * 8 + ii) * 256 + lane * 8;
        *(float4*)dst       = make_float4(lo2(acc2[ii][0]), hi2(acc2[ii][0]),
                                          lo2(acc2[ii][1]), hi2(acc2[ii][1]));
        *(float4*)(dst + 4) = make_float4(lo2(acc2[ii][2]), hi2(acc2[ii][2]),
                                          lo2(acc2[ii][3]), hi2(acc2[ii][3]));
    }
    // rowsum: 4 threads share one ih
    rs += __shfl_xor_sync(0xffffffffu, rs, 1);
    rs += __shfl_xor_sync(0xffffffffu, rs, 2);
    if ((t & 3) == 0) atomicAdd(&g_rowsum[b * 32 + (t >> 2)], rs);
}

// ---------------- upd = ((Σu + eps·L)/denom) @ Wv_h^T ----------------
__global__ void __launch_bounds__(256)
k_updproj(const float* __restrict__ Wv) {
    int b = blockIdx.x, dh2 = blockIdx.y;
    int t = threadIdx.x;
    int ihx = t >> 3, dq = (t & 7) * 4;
    int h = ihx & 3, i = ihx >> 2;
    int dbase = dh2 * 32;

    __shared__ __align__(16) float ss[32][256];
    __shared__ float Wvs[4][32][16];
    __shared__ float inv_s[32];

    if (t < 32) inv_s[t] = 1.f / (g_rowsum[b * 32 + t] + 4096.f * EPSF);
    __syncthreads();

#pragma unroll
    for (int q = 0; q < 8; q++) {
        int idx = t + 256 * q;
        int ih = idx >> 6, s4 = idx & 63;
        float4 Lv = *(const float4*)(g_L + b * 256 + s4 * 4);
        float4 a = make_float4(Lv.x * EPSF, Lv.y * EPSF, Lv.z * EPSF, Lv.w * EPSF);
#pragma unroll
        for (int p = 0; p < 32; p++) {
            float4 u = *(const float4*)(g_upart + ((size_t)(p * 1024) + b * 32 + ih) * 256 + s4 * 4);
            a.x += u.x; a.y += u.y; a.z += u.z; a.w += u.w;
        }
        float iv = inv_s[ih];
        a.x *= iv; a.y *= iv; a.z *= iv; a.w *= iv;
        *(float4*)&ss[ih][s4 * 4] = a;
    }

    float acc[4] = {0.f, 0.f, 0.f, 0.f};
    for (int cc = 0; cc < 16; cc++) {
        int c0 = cc * 16;
        __syncthreads();
#pragma unroll
        for (int q = 0; q < 8; q++) {
            int idx = t + 256 * q;
            int hh = idx >> 9, dd = (idx >> 4) & 31, c = idx & 15;
            Wvs[hh][dd][c] = Wv[(size_t)(hh * 64 + dbase + dd) * 256 + c0 + c];
        }
        __syncthreads();
#pragma unroll
        for (int c4 = 0; c4 < 4; c4++) {
            float4 sv = *(const float4*)&ss[ihx][c0 + c4 * 4];
#pragma unroll
            for (int k = 0; k < 4; k++) {
                const float* w = &Wvs[h][dq + k][c4 * 4];
                acc[k] += sv.x * w[0] + sv.y * w[1] + sv.z * w[2] + sv.w * w[3];
            }
        }
    }
#pragma unroll
    for (int k = 0; k < 4; k++)
        g_upd[(size_t)(b * 8 + i) * 256 + h * 64 + dbase + dq + k] = acc[k];
}

// ---------------- combined GRU gate GEMMs ----------------
__global__ void __launch_bounds__(256)
k_gates(const float* __restrict__ W_ih, const float* __restrict__ W_hh,
        const float* __restrict__ b_ih, const float* __restrict__ b_hh) {
    int mode = blockIdx.z;
    const float* A    = mode ? g_fill : g_upd;
    const float* W    = mode ? W_hh : W_ih;
    const float* bias = mode ? b_hh : b_ih;
    float* C = g_gates + mode * 196608;

    __shared__ float As[64][17];
    __shared__ float Bsx[64][17];
    int t = threadIdx.x;
    int row0 = blockIdx.x * 64, col0 = blockIdx.y * 64;
    int tx = t & 15, ty = t >> 4;

    float acc[4][4];
#pragma unroll
    for (int i = 0; i < 4; i++)
#pragma unroll
        for (int j = 0; j < 4; j++) acc[i][j] = 0.f;

    for (int k0 = 0; k0 < 256; k0 += 16) {
        __syncthreads();
        {
            int row = t >> 2, kp = t & 3;
            float4 a4 = *(const float4*)(A + (size_t)(row0 + row) * 256 + k0 + kp * 4);
            As[row][kp * 4 + 0] = a4.x; As[row][kp * 4 + 1] = a4.y;
            As[row][kp * 4 + 2] = a4.z; As[row][kp * 4 + 3] = a4.w;
            float4 b4 = *(const float4*)(W + (size_t)(col0 + row) * 256 + k0 + kp * 4);
            Bsx[row][kp * 4 + 0] = b4.x; Bsx[row][kp * 4 + 1] = b4.y;
            Bsx[row][kp * 4 + 2] = b4.z; Bsx[row][kp * 4 + 3] = b4.w;
        }
        __syncthreads();
#pragma unroll
        for (int kk = 0; kk < 16; kk++) {
            float a[4], bb[4];
#pragma unroll
            for (int i = 0; i < 4; i++) a[i]  = As[ty + 16 * i][kk];
#pragma unroll
            for (int j = 0; j < 4; j++) bb[j] = Bsx[tx + 16 * j][kk];
#pragma unroll
            for (int i = 0; i < 4; i++)
#pragma unroll
                for (int j = 0; j < 4; j++) acc[i][j] += a[i] * bb[j];
        }
    }
#pragma unroll
    for (int i = 0; i < 4; i++)
#pragma unroll
        for (int j = 0; j < 4; j++)
            C[(size_t)(row0 + ty + 16 * i) * 768 + col0 + tx + 16 * j] =
                acc[i][j] + bias[col0 + tx + 16 * j];
}

// ---------------- GRU elementwise ----------------
__global__ void k_gru() {
    int idx = blockIdx.x * blockDim.x + threadIdx.x;
    int r = idx >> 8, c = idx & 255;
    const float* gi = g_gates + (size_t)r * 768;
    const float* gh = g_gates + 196608 + (size_t)r * 768;
    float ir = gi[c], iz = gi[c + 256], in = gi[c + 512];
    float hr = gh[c], hz = gh[c + 256], hn = gh[c + 512];
    float rr = 1.f / (1.f + expf(-(ir + hr)));
    float zz = 1.f / (1.f + expf(-(iz + hz)));
    float nn = tanhf(in + rr * hn);
    float hp = g_fill[idx];
    g_fill[idx] = (1.f - zz) * nn + zz * hp;
}

__global__ void k_copyout(float* __restrict__ dst) {
    int idx = blockIdx.x * blockDim.x + threadIdx.x;
    dst[idx] = g_fill[idx];
}

// ---------------- launcher ----------------
extern "C" void kernel_launch(void* const* d_in, const int* in_sizes, int n_in,
                              void* d_out, int out_size) {
    const float* inputs = (const float*)d_in[0];
    const float* cond   = (const float*)d_in[1];
    const float* Wq     = (const float*)d_in[2];
    const float* Wk     = (const float*)d_in[3];
    const float* Wv     = (const float*)d_in[4];
    const float* W_ih   = (const float*)d_in[5];
    const float* W_hh   = (const float*)d_in[6];
    const float* b_ih   = (const float*)d_in[7];
    const float* b_hh   = (const float*)d_in[8];
    const float* lig    = (const float*)d_in[9];
    const float* lib    = (const float*)d_in[10];
    const float* lfg    = (const float*)d_in[11];
    const float* lfb    = (const float*)d_in[12];
    float* out = (float*)d_out;

    k_lnx2<<<dim3(32, 32), 256>>>(inputs, lig, lib);            // 1
    k_lsum<<<32, 256>>>();                                      // 2
    k_pcomp<<<dim3(4, 4, 4), 256>>>(Wq, Wk);                    // 3

    for (int it = 0; it < 3; it++) {
        k_lnfill<<<32, 256>>>(lfg, lfb, cond, it == 0);         // 4
        k_tgemm<<<dim3(32, 4), 256>>>();                        // 5
        k_fused<<<dim3(32, 32), 128>>>(it == 2 ? 1 : 0, out + 65536);  // 6
        k_updproj<<<dim3(32, 2), 256>>>(Wv);                    // 7
        k_gates<<<dim3(4, 12, 2), 256>>>(W_ih, W_hh, b_ih, b_hh); // 8
        k_gru<<<256, 256>>>();                                  // 9
    }
    k_copyout<<<64, 1024>>>(out);
}

// round 17
// speedup vs baseline: 1.2706x; 1.0078x over previous
#include <cuda_runtime.h>
#include <cstdint>
#include <math.h>

#define SCALEF 0.125f     // DH^-0.5
#define EPSF   1e-8f
#define LNEPS  1e-5f

// -------- scratch (device globals: allocation-free) --------
__device__ float g_lnx[33554432];         // LN(inputs) [b][j][256]
__device__ float g_Lpart[32 * 8192];      // per-jc column-sum partials
__device__ float g_L[8192];               // L[b][c] = sum_j lnx
__device__ float g_P[4 * 256 * 256];      // P_h = Wq_h^T Wk_h
__device__ float g_t[1024 * 256];         // t[(b,ih)][c] (SCALE folded)
__device__ float g_upart[32 * 1024 * 256];// u partials [js][(b,ih)][c]
__device__ float g_rowsum[1024];          // [b][ih]
__device__ float g_fill[65536];           // fillers
__device__ float g_upd[65536];            // updates
__device__ float g_gates[2 * 256 * 768];  // [gi|gh]

// ---------------- packed f32x2 helpers ----------------
__device__ __forceinline__ unsigned long long ffma2(unsigned long long a,
                                                    unsigned long long b,
                                                    unsigned long long c) {
    unsigned long long d;
    asm("fma.rn.f32x2 %0, %1, %2, %3;" : "=l"(d) : "l"(a), "l"(b), "l"(c));
    return d;
}
__device__ __forceinline__ unsigned long long bcast2(float x) {
    unsigned u = __float_as_uint(x);
    return ((unsigned long long)u << 32) | (unsigned long long)u;
}
__device__ __forceinline__ float lo2(unsigned long long v) { return __uint_as_float((unsigned)v); }
__device__ __forceinline__ float hi2(unsigned long long v) { return __uint_as_float((unsigned)(v >> 32)); }

// ---------------- fused row-stats + LN + column-sum partials ----------------
__global__ void __launch_bounds__(256)
k_lnx2(const float* __restrict__ x, const float* __restrict__ g,
       const float* __restrict__ b) {
    __shared__ float csm[8][256];

    int bb = blockIdx.x, jc = blockIdx.y;
    int t = threadIdx.x;
    int w = t >> 5, lane = t & 31;
    int row0 = bb * 4096 + jc * 128 + w * 16;

    float gg[8], bv[8];
#pragma unroll
    for (int u = 0; u < 8; u++) {
        gg[u] = g[lane + 32 * u];
        bv[u] = b[lane + 32 * u];
    }

    float csum[8];
#pragma unroll
    for (int u = 0; u < 8; u++) csum[u] = 0.f;

    for (int r = 0; r < 16; r++) {
        int row = row0 + r;
        const float* xr = x + (size_t)row * 256;
        float v[8];
        float s = 0.f;
#pragma unroll
        for (int u = 0; u < 8; u++) { v[u] = xr[lane + 32 * u]; s += v[u]; }
#pragma unroll
        for (int o = 16; o > 0; o >>= 1) s += __shfl_xor_sync(0xffffffffu, s, o);
        float m = s * (1.f / 256.f);
        float ss = 0.f;
#pragma unroll
        for (int u = 0; u < 8; u++) { float d = v[u] - m; ss += d * d; }
#pragma unroll
        for (int o = 16; o > 0; o >>= 1) ss += __shfl_xor_sync(0xffffffffu, ss, o);
        float rstd = rsqrtf(ss * (1.f / 256.f) + LNEPS);
        float* lr = g_lnx + (size_t)row * 256;
#pragma unroll
        for (int u = 0; u < 8; u++) {
            float o2 = (v[u] - m) * rstd * gg[u] + bv[u];
            lr[lane + 32 * u] = o2;
            csum[u] += o2;
        }
    }
#pragma unroll
    for (int u = 0; u < 8; u++) csm[w][lane + 32 * u] = csum[u];
    __syncthreads();
    float tot = 0.f;
#pragma unroll
    for (int w2 = 0; w2 < 8; w2++) tot += csm[w2][t];
    g_Lpart[jc * 8192 + bb * 256 + t] = tot;
}

// ---------------- L = sum of partials ----------------
__global__ void k_lsum() {
    int b = blockIdx.x, t = threadIdx.x;
    float s = 0.f;
#pragma unroll 8
    for (int jc = 0; jc < 32; jc++) s += g_Lpart[jc * 8192 + b * 256 + t];
    g_L[b * 256 + t] = s;
}

// ---------------- P_h = Wq_h^T @ Wk_h (once) ----------------
__global__ void __launch_bounds__(256)
k_pcomp(const float* __restrict__ Wq, const float* __restrict__ Wk) {
    int h = blockIdx.x, et = blockIdx.y, ct = blockIdx.z;
    int e0 = et * 64, c0 = ct * 64;
    int t = threadIdx.x;
    int tx = t & 15, ty = t >> 4;

    __shared__ float Qs[64][65];
    __shared__ float Ks[64][65];
    int d = t >> 2, sg = (t & 3) * 16;
#pragma unroll
    for (int q = 0; q < 4; q++) {
        float4 vq = *(const float4*)(Wq + (size_t)(h * 64 + d) * 256 + e0 + sg + q * 4);
        Qs[d][sg + q * 4 + 0] = vq.x; Qs[d][sg + q * 4 + 1] = vq.y;
        Qs[d][sg + q * 4 + 2] = vq.z; Qs[d][sg + q * 4 + 3] = vq.w;
        float4 vk = *(const float4*)(Wk + (size_t)(h * 64 + d) * 256 + c0 + sg + q * 4);
        Ks[d][sg + q * 4 + 0] = vk.x; Ks[d][sg + q * 4 + 1] = vk.y;
        Ks[d][sg + q * 4 + 2] = vk.z; Ks[d][sg + q * 4 + 3] = vk.w;
    }
    __syncthreads();
    float acc[4][4];
#pragma unroll
    for (int i = 0; i < 4; i++)
#pragma unroll
        for (int j = 0; j < 4; j++) acc[i][j] = 0.f;
    for (int dd = 0; dd < 64; dd++) {
        float a[4], bb[4];
#pragma unroll
        for (int i = 0; i < 4; i++) a[i] = Qs[dd][ty + 16 * i];
#pragma unroll
        for (int j = 0; j < 4; j++) bb[j] = Ks[dd][tx + 16 * j];
#pragma unroll
        for (int i = 0; i < 4; i++)
#pragma unroll
            for (int j = 0; j < 4; j++) acc[i][j] += a[i] * bb[j];
    }
#pragma unroll
    for (int i = 0; i < 4; i++)
#pragma unroll
        for (int j = 0; j < 4; j++)
            g_P[(size_t)h * 65536 + (size_t)(e0 + ty + 16 * i) * 256 + c0 + tx + 16 * j] = acc[i][j];
}

// ---------------- t = SCALE * LN(fill) @ P_h  (lnfill fused in) --------------
// grid (32 b, 4 ct), 256 threads. Each block LNs batch-b's 8 filler rows
// in-smem (redundant across ct — negligible), ct==0 also copies cond->fill
// on iter0 and zeroes rowsum.
__global__ void __launch_bounds__(256)
k_tgemm(const float* __restrict__ lg, const float* __restrict__ lb,
        const float* __restrict__ cond, int first) {
    int b = blockIdx.x, ct = blockIdx.y;
    int c0 = ct * 64;
    int t = threadIdx.x;
    int ihx = t >> 3, c8 = (t & 7) * 8;
    int h = ihx & 3, i = ihx >> 2;

    __shared__ float fs[2048];
    __shared__ __align__(16) float Ps[4][32][68];

    // ---- LN of the 8 filler rows (warp w = row w)
    {
        int w = t >> 5, lane = t & 31;
        int row = b * 8 + w;
        const float* r = (first ? cond : g_fill) + (size_t)row * 256;
        float v[8];
        float s = 0.f;
#pragma unroll
        for (int u = 0; u < 8; u++) { v[u] = r[lane + 32 * u]; s += v[u]; }
#pragma unroll
        for (int o = 16; o > 0; o >>= 1) s += __shfl_xor_sync(0xffffffffu, s, o);
        float m = s * (1.f / 256.f);
        float ss = 0.f;
#pragma unroll
        for (int u = 0; u < 8; u++) { float d = v[u] - m; ss += d * d; }
#pragma unroll
        for (int o = 16; o > 0; o >>= 1) ss += __shfl_xor_sync(0xffffffffu, ss, o);
        float rstd = rsqrtf(ss * (1.f / 256.f) + LNEPS);
#pragma unroll
        for (int u = 0; u < 8; u++) {
            int c = lane + 32 * u;
            if (first && ct == 0) g_fill[row * 256 + c] = v[u];
            fs[w * 256 + c] = (v[u] - m) * rstd * lg[c] + lb[c];
        }
        if (ct == 0 && t < 32) g_rowsum[b * 32 + t] = 0.f;
    }
    __syncthreads();

    unsigned long long acc[4] = {0ull, 0ull, 0ull, 0ull};

    for (int ec = 0; ec < 8; ec++) {
        int e0 = ec * 32;
        if (ec) __syncthreads();
#pragma unroll
        for (int q = 0; q < 8; q++) {
            int idx = t + 256 * q;
            int hh = idx >> 9, e = (idx >> 4) & 31, sg = idx & 15;
            float4 v = *(const float4*)(g_P + (size_t)hh * 65536 +
                                        (size_t)(e0 + e) * 256 + c0 + sg * 4);
            *(float4*)&Ps[hh][e][sg * 4] = v;
        }
        __syncthreads();
#pragma unroll
        for (int e = 0; e < 32; e++) {
            unsigned long long a = bcast2(fs[i * 256 + e0 + e]);
            ulonglong2 p0 = *(const ulonglong2*)&Ps[h][e][c8];
            ulonglong2 p1 = *(const ulonglong2*)&Ps[h][e][c8 + 4];
            acc[0] = ffma2(a, p0.x, acc[0]);
            acc[1] = ffma2(a, p0.y, acc[1]);
            acc[2] = ffma2(a, p1.x, acc[2]);
            acc[3] = ffma2(a, p1.y, acc[3]);
        }
    }
    int row = b * 32 + ihx;
#pragma unroll
    for (int q = 0; q < 4; q++) {
        g_t[(size_t)row * 256 + c0 + c8 + 2 * q]     = SCALEF * lo2(acc[q]);
        g_t[(size_t)row * 256 + c0 + c8 + 2 * q + 1] = SCALEF * hi2(acc[q]);
    }
}

// ---------------- fused: dots + inverted softmax + u-accumulation ------------
// grid (32 b, 32 js of 128 j), 128 threads, 36.8KB static smem -> 6 blocks/SM.
// Phase 1 software-pipelined (register prefetch).
__global__ void __launch_bounds__(128)
k_fused(int last, float* __restrict__ attn_out) {
    __shared__ __align__(16) float dsm[32 * 132];            // dots/attn [ih][j]
    __shared__ __align__(16) float Bs[16 * 260];             // lnx tile (both phases)
    __shared__ __align__(16) unsigned long long t2[32 * 16]; // a-operand (u64 bcast)

    int b = blockIdx.x, js = blockIdx.y;
    int t = threadIdx.x;
    int ihg = t >> 5;          // warp id: ih group of 8
    int lane = t & 31;         // phase1: 4-j group; phase2: 8-c group
    int j0 = js * 128;

    const float* lnxb = g_lnx + (size_t)b * 4096 * 256;

    unsigned long long acc1[8][2];
#pragma unroll
    for (int ii = 0; ii < 8; ii++) { acc1[ii][0] = 0ull; acc1[ii][1] = 0ull; }

    int p1_ih = t >> 2, p1_cq = (t & 3) * 4;
    const float* p1_tsrc = g_t + (size_t)(b * 32 + p1_ih) * 256 + p1_cq;
    int p1_j[4], p1_f4[4];
#pragma unroll
    for (int q = 0; q < 4; q++) {
        int idx = t + 128 * q;
        p1_j[q]  = idx >> 2;
        p1_f4[q] = (idx & 3) * 4;
    }

    // ---------- phase 1 (pipelined): dots[ih][j] over c ----------
    float4 treg = *(const float4*)(p1_tsrc);
    float4 breg[4];
#pragma unroll
    for (int q = 0; q < 4; q++)
        breg[q] = *(const float4*)(lnxb + (size_t)(j0 + p1_j[q]) * 256 + p1_f4[q]);

    for (int cc = 0; cc < 16; cc++) {
        t2[p1_ih * 16 + p1_cq + 0] = bcast2(treg.x);
        t2[p1_ih * 16 + p1_cq + 1] = bcast2(treg.y);
        t2[p1_ih * 16 + p1_cq + 2] = bcast2(treg.z);
        t2[p1_ih * 16 + p1_cq + 3] = bcast2(treg.w);
#pragma unroll
        for (int q = 0; q < 4; q++) {
            Bs[(p1_f4[q] + 0) * 132 + p1_j[q]] = breg[q].x;
            Bs[(p1_f4[q] + 1) * 132 + p1_j[q]] = breg[q].y;
            Bs[(p1_f4[q] + 2) * 132 + p1_j[q]] = breg[q].z;
            Bs[(p1_f4[q] + 3) * 132 + p1_j[q]] = breg[q].w;
        }
        __syncthreads();

        if (cc < 15) {
            int c0n = (cc + 1) * 16;
            treg = *(const float4*)(p1_tsrc + c0n);
#pragma unroll
            for (int q = 0; q < 4; q++)
                breg[q] = *(const float4*)(lnxb + (size_t)(j0 + p1_j[q]) * 256 + c0n + p1_f4[q]);
        }

#pragma unroll
        for (int c = 0; c < 16; c++) {
            ulonglong2 b0 = *(const ulonglong2*)&Bs[c * 132 + lane * 4];
#pragma unroll
            for (int ii = 0; ii < 8; ii++) {
                unsigned long long a = t2[(ihg * 8 + ii) * 16 + c];
                acc1[ii][0] = ffma2(a, b0.x, acc1[ii][0]);
                acc1[ii][1] = ffma2(a, b0.y, acc1[ii][1]);
            }
        }
        __syncthreads();
    }
#pragma unroll
    for (int ii = 0; ii < 8; ii++)
        *(float4*)&dsm[(ihg * 8 + ii) * 132 + lane * 4] = make_float4(
            lo2(acc1[ii][0]), hi2(acc1[ii][0]), lo2(acc1[ii][1]), hi2(acc1[ii][1]));
    __syncthreads();

    // ---------- softmax over 32 (slot,head) per column j = t ----------
    {
        int j = t;
        float vcol[32], mx = -1e30f;
#pragma unroll
        for (int ih = 0; ih < 32; ih++) { vcol[ih] = dsm[ih * 132 + j]; mx = fmaxf(mx, vcol[ih]); }
        float sum = 0.f;
#pragma unroll
        for (int ih = 0; ih < 32; ih++) { vcol[ih] = __expf(vcol[ih] - mx); sum += vcol[ih]; }
        float inv = 1.f / sum;
#pragma unroll
        for (int ih = 0; ih < 32; ih++) { vcol[ih] *= inv; dsm[ih * 132 + j] = vcol[ih]; }
        if (last) {
#pragma unroll
            for (int i = 0; i < 8; i++)
                attn_out[((size_t)b * 8 + i) * 4096 + j0 + j] =
                    0.25f * (vcol[4 * i] + vcol[4 * i + 1] + vcol[4 * i + 2] + vcol[4 * i + 3]);
        }
    }

    // ---------- phase 2: u[ih][c] += attn[ih][j] * lnx[j][c] ----------
    unsigned long long acc2[8][4];
#pragma unroll
    for (int ii = 0; ii < 8; ii++)
#pragma unroll
        for (int q = 0; q < 4; q++) acc2[ii][q] = 0ull;
    float rs = 0.f;

    for (int jt = 0; jt < 8; jt++) {
        int jb = jt * 16;
        __syncthreads();
#pragma unroll
        for (int q = 0; q < 8; q++) {
            int idx = t + 128 * q;
            int r = idx >> 6, f4 = idx & 63;
            *(float4*)&Bs[r * 260 + f4 * 4] =
                *(const float4*)(lnxb + (size_t)(j0 + jb + r) * 256 + f4 * 4);
        }
        {
            int ih = t >> 2, jq = (t & 3) * 4;
#pragma unroll
            for (int k = 0; k < 4; k++) {
                float a = dsm[ih * 132 + jb + jq + k];
                rs += a;
                t2[ih * 16 + jq + k] = bcast2(a);
            }
        }
        __syncthreads();
#pragma unroll
        for (int j = 0; j < 16; j++) {
            ulonglong2 b0 = *(const ulonglong2*)&Bs[j * 260 + lane * 8];
            ulonglong2 b1 = *(const ulonglong2*)&Bs[j * 260 + lane * 8 + 4];
#pragma unroll
            for (int ii = 0; ii < 8; ii++) {
                unsigned long long a = t2[(ihg * 8 + ii) * 16 + j];
                acc2[ii][0] = ffma2(a, b0.x, acc2[ii][0]);
                acc2[ii][1] = ffma2(a, b0.y, acc2[ii][1]);
                acc2[ii][2] = ffma2(a, b1.x, acc2[ii][2]);
                acc2[ii][3] = ffma2(a, b1.y, acc2[ii][3]);
            }
        }
    }

#pragma unroll
    for (int ii = 0; ii < 8; ii++) {
        float* dst = g_upart + ((size_t)(js * 1024) + b * 32 + ihg * 8 + ii) * 256 + lane * 8;
        *(float4*)dst       = make_float4(lo2(acc2[ii][0]), hi2(acc2[ii][0]),
                                          lo2(acc2[ii][1]), hi2(acc2[ii][1]));
        *(float4*)(dst + 4) = make_float4(lo2(acc2[ii][2]), hi2(acc2[ii][2]),
                                          lo2(acc2[ii][3]), hi2(acc2[ii][3]));
    }
    rs += __shfl_xor_sync(0xffffffffu, rs, 1);
    rs += __shfl_xor_sync(0xffffffffu, rs, 2);
    if ((t & 3) == 0) atomicAdd(&g_rowsum[b * 32 + (t >> 2)], rs);
}

// ---------------- upd = ((Σu + eps·L)/denom) @ Wv_h^T ----------------
__global__ void __launch_bounds__(256)
k_updproj(const float* __restrict__ Wv) {
    int b = blockIdx.x, dh2 = blockIdx.y;
    int t = threadIdx.x;
    int ihx = t >> 3, dq = (t & 7) * 4;
    int h = ihx & 3, i = ihx >> 2;
    int dbase = dh2 * 32;

    __shared__ __align__(16) float ss[32][256];
    __shared__ float Wvs[4][32][16];
    __shared__ float inv_s[32];

    if (t < 32) inv_s[t] = 1.f / (g_rowsum[b * 32 + t] + 4096.f * EPSF);
    __syncthreads();

#pragma unroll
    for (int q = 0; q < 8; q++) {
        int idx = t + 256 * q;
        int ih = idx >> 6, s4 = idx & 63;
        float4 Lv = *(const float4*)(g_L + b * 256 + s4 * 4);
        float4 a = make_float4(Lv.x * EPSF, Lv.y * EPSF, Lv.z * EPSF, Lv.w * EPSF);
#pragma unroll
        for (int p = 0; p < 32; p++) {
            float4 u = *(const float4*)(g_upart + ((size_t)(p * 1024) + b * 32 + ih) * 256 + s4 * 4);
            a.x += u.x; a.y += u.y; a.z += u.z; a.w += u.w;
        }
        float iv = inv_s[ih];
        a.x *= iv; a.y *= iv; a.z *= iv; a.w *= iv;
        *(float4*)&ss[ih][s4 * 4] = a;
    }

    float acc[4] = {0.f, 0.f, 0.f, 0.f};
    for (int cc = 0; cc < 16; cc++) {
        int c0 = cc * 16;
        __syncthreads();
#pragma unroll
        for (int q = 0; q < 8; q++) {
            int idx = t + 256 * q;
            int hh = idx >> 9, dd = (idx >> 4) & 31, c = idx & 15;
            Wvs[hh][dd][c] = Wv[(size_t)(hh * 64 + dbase + dd) * 256 + c0 + c];
        }
        __syncthreads();
#pragma unroll
        for (int c4 = 0; c4 < 4; c4++) {
            float4 sv = *(const float4*)&ss[ihx][c0 + c4 * 4];
#pragma unroll
            for (int k = 0; k < 4; k++) {
                const float* w = &Wvs[h][dq + k][c4 * 4];
                acc[k] += sv.x * w[0] + sv.y * w[1] + sv.z * w[2] + sv.w * w[3];
            }
        }
    }
#pragma unroll
    for (int k = 0; k < 4; k++)
        g_upd[(size_t)(b * 8 + i) * 256 + h * 64 + dbase + dq + k] = acc[k];
}

// ---------------- combined GRU gate GEMMs ----------------
__global__ void __launch_bounds__(256)
k_gates(const float* __restrict__ W_ih, const float* __restrict__ W_hh,
        const float* __restrict__ b_ih, const float* __restrict__ b_hh) {
    int mode = blockIdx.z;
    const float* A    = mode ? g_fill : g_upd;
    const float* W    = mode ? W_hh : W_ih;
    const float* bias = mode ? b_hh : b_ih;
    float* C = g_gates + mode * 196608;

    __shared__ float As[64][17];
    __shared__ float Bsx[64][17];
    int t = threadIdx.x;
    int row0 = blockIdx.x * 64, col0 = blockIdx.y * 64;
    int tx = t & 15, ty = t >> 4;

    float acc[4][4];
#pragma unroll
    for (int i = 0; i < 4; i++)
#pragma unroll
        for (int j = 0; j < 4; j++) acc[i][j] = 0.f;

    for (int k0 = 0; k0 < 256; k0 += 16) {
        __syncthreads();
        {
            int row = t >> 2, kp = t & 3;
            float4 a4 = *(const float4*)(A + (size_t)(row0 + row) * 256 + k0 + kp * 4);
            As[row][kp * 4 + 0] = a4.x; As[row][kp * 4 + 1] = a4.y;
            As[row][kp * 4 + 2] = a4.z; As[row][kp * 4 + 3] = a4.w;
            float4 b4 = *(const float4*)(W + (size_t)(col0 + row) * 256 + k0 + kp * 4);
            Bsx[row][kp * 4 + 0] = b4.x; Bsx[row][kp * 4 + 1] = b4.y;
            Bsx[row][kp * 4 + 2] = b4.z; Bsx[row][kp * 4 + 3] = b4.w;
        }
        __syncthreads();
#pragma unroll
        for (int kk = 0; kk < 16; kk++) {
            float a[4], bb[4];
#pragma unroll
            for (int i = 0; i < 4; i++) a[i]  = As[ty + 16 * i][kk];
#pragma unroll
            for (int j = 0; j < 4; j++) bb[j] = Bsx[tx + 16 * j][kk];
#pragma unroll
            for (int i = 0; i < 4; i++)
#pragma unroll
                for (int j = 0; j < 4; j++) acc[i][j] += a[i] * bb[j];
        }
    }
#pragma unroll
    for (int i = 0; i < 4; i++)
#pragma unroll
        for (int j = 0; j < 4; j++)
            C[(size_t)(row0 + ty + 16 * i) * 768 + col0 + tx + 16 * j] =
                acc[i][j] + bias[col0 + tx + 16 * j];
}

// ---------------- GRU elementwise ----------------
__global__ void k_gru() {
    int idx = blockIdx.x * blockDim.x + threadIdx.x;
    int r = idx >> 8, c = idx & 255;
    const float* gi = g_gates + (size_t)r * 768;
    const float* gh = g_gates + 196608 + (size_t)r * 768;
    float ir = gi[c], iz = gi[c + 256], in = gi[c + 512];
    float hr = gh[c], hz = gh[c + 256], hn = gh[c + 512];
    float rr = 1.f / (1.f + expf(-(ir + hr)));
    float zz = 1.f / (1.f + expf(-(iz + hz)));
    float nn = tanhf(in + rr * hn);
    float hp = g_fill[idx];
    g_fill[idx] = (1.f - zz) * nn + zz * hp;
}

__global__ void k_copyout(float* __restrict__ dst) {
    int idx = blockIdx.x * blockDim.x + threadIdx.x;
    dst[idx] = g_fill[idx];
}

// ---------------- launcher ----------------
extern "C" void kernel_launch(void* const* d_in, const int* in_sizes, int n_in,
                              void* d_out, int out_size) {
    const float* inputs = (const float*)d_in[0];
    const float* cond   = (const float*)d_in[1];
    const float* Wq     = (const float*)d_in[2];
    const float* Wk     = (const float*)d_in[3];
    const float* Wv     = (const float*)d_in[4];
    const float* W_ih   = (const float*)d_in[5];
    const float* W_hh   = (const float*)d_in[6];
    const float* b_ih   = (const float*)d_in[7];
    const float* b_hh   = (const float*)d_in[8];
    const float* lig    = (const float*)d_in[9];
    const float* lib    = (const float*)d_in[10];
    const float* lfg    = (const float*)d_in[11];
    const float* lfb    = (const float*)d_in[12];
    float* out = (float*)d_out;

    k_lnx2<<<dim3(32, 32), 256>>>(inputs, lig, lib);            // 1
    k_lsum<<<32, 256>>>();                                      // 2
    k_pcomp<<<dim3(4, 4, 4), 256>>>(Wq, Wk);                    // 3

    for (int it = 0; it < 3; it++) {
        k_tgemm<<<dim3(32, 4), 256>>>(lfg, lfb, cond, it == 0); // 4 (lnfill fused)
        k_fused<<<dim3(32, 32), 128>>>(it == 2 ? 1 : 0, out + 65536);  // 5
        k_updproj<<<dim3(32, 2), 256>>>(Wv);                    // 6
        k_gates<<<dim3(4, 12, 2), 256>>>(W_ih, W_hh, b_ih, b_hh); // 7
        k_gru<<<256, 256>>>();                                  // 8
    }
    k_copyout<<<64, 1024>>>(out);
}